// round 6
// baseline (speedup 1.0000x reference)
#include <cuda_runtime.h>
#include <cuda_fp16.h>
#include <mma.h>
#include <math.h>
#include <stdint.h>

using namespace nvcuda;

#define NN 50000
#define NE 800000
#define TILE 128
#define NT 6250          // NE / TILE
#define K1_GRID 148

// ---------------- scratch (device globals) ----------------
__device__ float g_f0[NN * 64];
__device__ float g_f1[NN * 192];          // [n][3][64]
__device__ float g_agg0[NN * 64];
__device__ float g_agg1[NN * 192];        // [n][3][64]
__device__ float g_z[NN * 8];
__device__ unsigned int g_amax[NN * 8];
__device__ __half g_wattn_h[256000000];   // E*320
__device__ __half g_msg0_h[51200000];     // E*64
__device__ __half g_msg1_h[153600000];    // E*192, [e][comp][64]
__device__ float g_a[6400000];            // E*8

// ---------------- helpers ----------------
__device__ __forceinline__ float siluf(float x) { return x / (1.f + expf(-x)); }
__device__ __forceinline__ float sigf(float x) { return 1.f / (1.f + expf(-x)); }
__device__ __forceinline__ unsigned int encf(float f) {
    unsigned int u = __float_as_uint(f);
    return (u & 0x80000000u) ? ~u : (u | 0x80000000u);
}
__device__ __forceinline__ float decf(unsigned int u) {
    return (u & 0x80000000u) ? __uint_as_float(u ^ 0x80000000u) : __uint_as_float(~u);
}

// ---------------- smem layout for k1 (byte offsets) ----------------
#define O_W1    0         // 64x64 f16
#define O_W2    8192
#define O_WDEG  16384     // 64x128
#define O_WATTN 32768     // 64x320
#define O_P0    73728
#define O_P1    81920
#define O_BIAS  90112     // 640 floats: b1|b2|bdeg(128)|battn(320)|expw
#define O_A     92672     // 8 warps x 16x64 f16
#define O_H2    109056    // 8 warps x 16x64 f16
#define O_STAGE 125440    // 8 warps x 16x64 f32
#define O_SY    158208    // 8 warps x 5x16 f32 (y0,y1,y2,cut,expd)
#define O_SDST  160768    // 8 warps x 16 int
#define K1_SMEM 161280

// ---------------- K0: init node state ----------------
__global__ void k0_init(const float* __restrict__ embed_W, const int* __restrict__ node_atom) {
    int stride = gridDim.x * blockDim.x;
    for (int i = blockIdx.x * blockDim.x + threadIdx.x; i < NN * 192; i += stride) {
        g_f1[i] = 0.f;
        g_agg1[i] = 0.f;
        if (i < NN * 64) {
            int n = i >> 6, c = i & 63;
            g_f0[i] = embed_W[node_atom[n] * 64 + c];
            g_agg0[i] = 0.f;
        }
        if (i < NN * 8) {
            g_amax[i] = 0x007FFFFFu;
            g_z[i] = 0.f;
        }
    }
}

// weights to smem fp16 row-major [64][N] (rows k >= Kdim zero-padded)
__device__ __forceinline__ void load_w_f16(const float* __restrict__ G, int Kdim, int Ncols,
                                           __half* dst, int tid, int nthreads) {
    for (int i = tid; i < 64 * Ncols; i += nthreads) {
        int k = i / Ncols, n = i - k * Ncols;
        dst[i] = __float2half((k < Kdim) ? G[k * Ncols + n] : 0.f);
    }
}

// warp-scope GEMM: C(16 x 64) = A(16x64 f16, ld 64) @ W[:, colbase:colbase+64] (ld ldw)
// results left in 4 accumulator fragments
#define WMMA_GEMM(Aptr, Wptr, ldw, colbase, acc) do { \
    wmma::fragment<wmma::matrix_a, 16, 16, 16, __half, wmma::row_major> _af; \
    wmma::fragment<wmma::matrix_b, 16, 16, 16, __half, wmma::row_major> _bf; \
    for (int _n = 0; _n < 4; _n++) wmma::fill_fragment(acc[_n], 0.f); \
    for (int _k = 0; _k < 4; _k++) { \
        wmma::load_matrix_sync(_af, (Aptr) + _k * 16, 64); \
        for (int _n = 0; _n < 4; _n++) { \
            wmma::load_matrix_sync(_bf, (Wptr) + (_k * 16) * (ldw) + (colbase) + _n * 16, (ldw)); \
            wmma::mma_sync(acc[_n], _af, _bf, acc[_n]); \
        } \
    } \
} while (0)

#define STORE_ACC(acc, stg) do { \
    for (int _n = 0; _n < 4; _n++) \
        wmma::store_matrix_sync((stg) + _n * 16, acc[_n], 64, wmma::mem_row_major); \
    __syncwarp(); \
} while (0)

// ---------------- K1: persistent WMMA edge pipeline ----------------
__global__ void __launch_bounds__(256, 1) k1_edge(
    const float* __restrict__ pos, const float* __restrict__ exp_w,
    const float* __restrict__ W1, const float* __restrict__ b1,
    const float* __restrict__ W2, const float* __restrict__ b2,
    const float* __restrict__ Wdeg, const float* __restrict__ bdeg,
    const float* __restrict__ Wattn, const float* __restrict__ battn,
    const float* __restrict__ P0, const float* __restrict__ P1,
    const int* __restrict__ esrc, const int* __restrict__ edst)
{
    extern __shared__ char sm[];
    __half* sW1 = reinterpret_cast<__half*>(sm + O_W1);
    __half* sW2 = reinterpret_cast<__half*>(sm + O_W2);
    __half* sWdeg = reinterpret_cast<__half*>(sm + O_WDEG);
    __half* sWattn = reinterpret_cast<__half*>(sm + O_WATTN);
    __half* sP0 = reinterpret_cast<__half*>(sm + O_P0);
    __half* sP1 = reinterpret_cast<__half*>(sm + O_P1);
    float* sbias = reinterpret_cast<float*>(sm + O_BIAS);

    int tid = threadIdx.x;
    int warp = tid >> 5, lane = tid & 31;

    __half* A  = reinterpret_cast<__half*>(sm + O_A) + warp * 1024;
    __half* H2 = reinterpret_cast<__half*>(sm + O_H2) + warp * 1024;
    float* stg = reinterpret_cast<float*>(sm + O_STAGE) + warp * 1024;
    float* syw = reinterpret_cast<float*>(sm + O_SY) + warp * 80;     // [5][16]
    int* sdw = reinterpret_cast<int*>(sm + O_SDST) + warp * 16;

    // ---- one-time weight/bias staging ----
    load_w_f16(W1, 50, 64, sW1, tid, 256);
    load_w_f16(W2, 64, 64, sW2, tid, 256);
    load_w_f16(Wdeg, 64, 128, sWdeg, tid, 256);
    load_w_f16(Wattn, 64, 320, sWattn, tid, 256);
    load_w_f16(P0, 64, 64, sP0, tid, 256);
    load_w_f16(P1, 64, 64, sP1, tid, 256);
    for (int i = tid; i < 640; i += 256) {
        float v;
        if (i < 64) v = b1[i];
        else if (i < 128) v = b2[i - 64];
        else if (i < 256) v = bdeg[i - 128];
        else if (i < 576) v = battn[i - 256];
        else v = exp_w[i - 576];
        sbias[i] = v;
    }
    __syncthreads();

    const float START = 0.006737946999085467f;   // exp(-5)
    const float STEP = (1.0f - START) / 49.0f;
    const float BETA = 1.0f / ((0.04f * (1.0f - START)) * (0.04f * (1.0f - START)));
    const float PI_ = 3.14159265358979323846f;
    const float INV = 0.25f;

    wmma::fragment<wmma::accumulator, 16, 16, 16, float> acc[4];

    for (int t = blockIdx.x; t < NT; t += gridDim.x) {
        int ew = t * TILE + warp * 16;    // this warp's 16 edges

        // ---- geometry: lanes 0..15, one edge each ----
        if (lane < 16) {
            int e = ew + lane;
            int s = esrc[e], d = edst[e];
            float vx = pos[d * 3 + 0] - pos[s * 3 + 0];
            float vy = pos[d * 3 + 1] - pos[s * 3 + 1];
            float vz = pos[d * 3 + 2] - pos[s * 3 + 2];
            float dist = sqrtf(vx * vx + vy * vy + vz * vz + 1e-9f);
            float ri = 1.f / dist;
            sdw[lane] = d;
            syw[0 * 16 + lane] = vx * ri;
            syw[1 * 16 + lane] = vy * ri;
            syw[2 * 16 + lane] = vz * ri;
            syw[3 * 16 + lane] = (dist < 5.0f) ? 0.5f * (cosf(PI_ * dist * 0.2f) + 1.f) : 0.f;
            syw[4 * 16 + lane] = expf(-dist);
        }
        __syncwarp();

        // ---- RBF into A[16][64] fp16 ----
        for (int i = lane; i < 1024; i += 32) {
            int row = i >> 6, k = i & 63;
            float v = 0.f;
            if (k < 50) {
                float tt = syw[4 * 16 + row] - (START + (float)k * STEP);
                v = syw[3 * 16 + row] * expf(-BETA * tt * tt);
            }
            A[i] = __float2half(v);
        }
        __syncwarp();

        // ---- GEMM1: rbf @ W1 -> silu -> A ----
        WMMA_GEMM(A, sW1, 64, 0, acc);
        STORE_ACC(acc, stg);
        for (int i = lane; i < 1024; i += 32) {
            int c = i & 63;
            A[i] = __float2half(siluf(stg[i] + sbias[c]));
        }
        __syncwarp();

        // ---- GEMM2: h1 @ W2 -> silu -> H2 ----
        WMMA_GEMM(A, sW2, 64, 0, acc);
        STORE_ACC(acc, stg);
        for (int i = lane; i < 1024; i += 32) {
            int c = i & 63;
            H2[i] = __float2half(siluf(stg[i] + sbias[64 + c]));
        }
        __syncwarp();

        // ---- w_attn: 5 chunks of 64 -> global fp16 ----
        for (int ch = 0; ch < 5; ch++) {
            WMMA_GEMM(H2, sWattn, 320, ch * 64, acc);
            STORE_ACC(acc, stg);
            for (int i = lane; i < 1024; i += 32) {
                int row = i >> 6, c = i & 63;
                float v = stg[i] + sbias[256 + ch * 64 + c];
                g_wattn_h[(long long)(ew + row) * 320 + ch * 64 + c] = __float2half(v);
            }
            __syncwarp();
        }

        // ---- deg path: ch0 -> P0 -> f0; ch1 -> P1 -> f1 ----
        for (int ch = 0; ch < 2; ch++) {
            WMMA_GEMM(H2, sWdeg, 128, ch * 64, acc);
            STORE_ACC(acc, stg);
            for (int i = lane; i < 1024; i += 32) {
                int c = i & 63;
                A[i] = __float2half((stg[i] + sbias[128 + ch * 64 + c]) * sbias[576 + c]);
            }
            __syncwarp();

            WMMA_GEMM(A, (ch == 0 ? sP0 : sP1), 64, 0, acc);
            STORE_ACC(acc, stg);
            if (ch == 0) {
                for (int i = lane; i < 1024; i += 32) {
                    int row = i >> 6, c = i & 63;
                    atomicAdd(&g_f0[sdw[row] * 64 + c], INV * stg[i]);
                }
            } else {
                for (int i = lane; i < 1024; i += 32) {
                    int row = i >> 6, c = i & 63;
                    float v = INV * stg[i];
                    float* pp = &g_f1[sdw[row] * 192];
                    atomicAdd(pp + 0 * 64 + c, v * syw[0 * 16 + row]);
                    atomicAdd(pp + 1 * 64 + c, v * syw[1 * 16 + row]);
                    atomicAdd(pp + 2 * 64 + c, v * syw[2 * 16 + row]);
                }
            }
            __syncwarp();
        }
    }
}

// ---------------- K2: messages + logits + segment max ----------------
__global__ void __launch_bounds__(256) k2_msg(
    const float* __restrict__ pos, const float* __restrict__ alpha_dot,
    const int* __restrict__ esrc, const int* __restrict__ edst)
{
    int warp = threadIdx.x >> 5, lane = threadIdx.x & 31;
    int e = blockIdx.x * 8 + warp;
    if (e >= NE) return;
    int s = esrc[e], d = edst[e];
    float vx = pos[d * 3 + 0] - pos[s * 3 + 0];
    float vy = pos[d * 3 + 1] - pos[s * 3 + 1];
    float vz = pos[d * 3 + 2] - pos[s * 3 + 2];
    float ri = rsqrtf(vx * vx + vy * vy + vz * vz + 1e-9f);
    float y0 = vx * ri, y1 = vy * ri, y2 = vz * ri;

    int c0 = lane, c1 = lane + 32;
    float s0a = g_f0[s * 64 + c0], s0b = g_f0[s * 64 + c1];
    const float* f1p = &g_f1[s * 192];
    float sa0 = f1p[0 * 64 + c0], sa1 = f1p[1 * 64 + c0], sa2 = f1p[2 * 64 + c0];
    float sb0 = f1p[0 * 64 + c1], sb1 = f1p[1 * 64 + c1], sb2 = f1p[2 * 64 + c1];

    long long wb = (long long)e * 320;
    float w0a = __half2float(g_wattn_h[wb + c0]),       w0b = __half2float(g_wattn_h[wb + c1]);
    float w1a = __half2float(g_wattn_h[wb + 64 + c0]),  w1b = __half2float(g_wattn_h[wb + 64 + c1]);
    float w2a = __half2float(g_wattn_h[wb + 128 + c0]), w2b = __half2float(g_wattn_h[wb + 128 + c1]);
    float w3a = __half2float(g_wattn_h[wb + 192 + c0]), w3b = __half2float(g_wattn_h[wb + 192 + c1]);
    float w4a = __half2float(g_wattn_h[wb + 256 + c0]), w4b = __half2float(g_wattn_h[wb + 256 + c1]);

    const float IS3 = 0.57735026918962576f;
    const float IS2 = 0.70710678118654752f;

    float dva = sa0 * y0 + sa1 * y1 + sa2 * y2;
    float dvb = sb0 * y0 + sb1 * y1 + sb2 * y2;
    float m0a = w0a * s0a + w3a * dva * IS3;
    float m0b = w0b * s0b + w3b * dvb * IS3;

    float cxa0 = sa1 * y2 - sa2 * y1, cxa1 = sa2 * y0 - sa0 * y2, cxa2 = sa0 * y1 - sa1 * y0;
    float cxb0 = sb1 * y2 - sb2 * y1, cxb1 = sb2 * y0 - sb0 * y2, cxb2 = sb0 * y1 - sb1 * y0;
    float w1sa = w1a * s0a, w1sb = w1b * s0b;
    float m1a0 = w1sa * y0 + w2a * sa0 + w4a * cxa0 * IS2;
    float m1a1 = w1sa * y1 + w2a * sa1 + w4a * cxa1 * IS2;
    float m1a2 = w1sa * y2 + w2a * sa2 + w4a * cxa2 * IS2;
    float m1b0 = w1sb * y0 + w2b * sb0 + w4b * cxb0 * IS2;
    float m1b1 = w1sb * y1 + w2b * sb1 + w4b * cxb1 * IS2;
    float m1b2 = w1sb * y2 + w2b * sb2 + w4b * cxb2 * IS2;

    long long mb0 = (long long)e * 64, mb1 = (long long)e * 192;
    g_msg0_h[mb0 + c0] = __float2half(m0a);
    g_msg0_h[mb0 + c1] = __float2half(m0b);
    g_msg1_h[mb1 + 0 * 64 + c0] = __float2half(m1a0);
    g_msg1_h[mb1 + 1 * 64 + c0] = __float2half(m1a1);
    g_msg1_h[mb1 + 2 * 64 + c0] = __float2half(m1a2);
    g_msg1_h[mb1 + 0 * 64 + c1] = __float2half(m1b0);
    g_msg1_h[mb1 + 1 * 64 + c1] = __float2half(m1b1);
    g_msg1_h[mb1 + 2 * 64 + c1] = __float2half(m1b2);

    float slra = 0.2f * m0a + 0.8f * m0a * sigf(m0a);
    float slrb = 0.2f * m0b + 0.8f * m0b * sigf(m0b);
    float pa = slra * alpha_dot[c0];
    float pb = slrb * alpha_dot[c1];
#pragma unroll
    for (int off = 4; off; off >>= 1) {
        pa += __shfl_xor_sync(0xffffffffu, pa, off);
        pb += __shfl_xor_sync(0xffffffffu, pb, off);
    }
    if ((lane & 7) == 0) {
        int h0 = lane >> 3;
        g_a[(long long)e * 8 + h0] = pa;
        g_a[(long long)e * 8 + h0 + 4] = pb;
        atomicMax(&g_amax[d * 8 + h0], encf(pa));
        atomicMax(&g_amax[d * 8 + h0 + 4], encf(pb));
    }
}

// ---------------- K3: exp + fused (z, ea*msg) scatter ----------------
__global__ void __launch_bounds__(256) k3_agg(const int* __restrict__ edst) {
    int warp = threadIdx.x >> 5, lane = threadIdx.x & 31;
    int e = blockIdx.x * 8 + warp;
    if (e >= NE) return;
    int d = edst[e];
    int h0 = lane >> 3, h1 = 4 + (lane >> 3);
    float aa = g_a[(long long)e * 8 + h0];
    float ab = g_a[(long long)e * 8 + h1];
    float ma = decf(g_amax[d * 8 + h0]);
    float mb = decf(g_amax[d * 8 + h1]);
    float eaa = expf(aa - ma), eab = expf(ab - mb);
    if ((lane & 7) == 0) {
        atomicAdd(&g_z[d * 8 + h0], eaa);
        atomicAdd(&g_z[d * 8 + h1], eab);
    }
    long long mb0 = (long long)e * 64, mb1 = (long long)e * 192;
    int c0 = lane, c1 = lane + 32;
    atomicAdd(&g_agg0[d * 64 + c0], eaa * __half2float(g_msg0_h[mb0 + c0]));
    atomicAdd(&g_agg0[d * 64 + c1], eab * __half2float(g_msg0_h[mb0 + c1]));
#pragma unroll
    for (int i = 0; i < 3; i++) {
        atomicAdd(&g_agg1[d * 192 + i * 64 + c0], eaa * __half2float(g_msg1_h[mb1 + i * 64 + c0]));
        atomicAdd(&g_agg1[d * 192 + i * 64 + c1], eab * __half2float(g_msg1_h[mb1 + i * 64 + c1]));
    }
}

// ---------------- K4: node update ----------------
__global__ void __launch_bounds__(256) k4_node(
    const float* __restrict__ P0, const float* __restrict__ P1,
    const float* __restrict__ W1s, const float* __restrict__ b1s,
    const float* __restrict__ W1v, const float* __restrict__ W2s,
    const float* __restrict__ b2s, const float* __restrict__ W2v,
    float* __restrict__ out)
{
    __shared__ float sm[8][832];
    int warp = threadIdx.x >> 5, lane = threadIdx.x & 31;
    int n = blockIdx.x * 8 + warp;
    if (n >= NN) return;
    float* sA0 = sm[warp];
    float* sA1 = sm[warp] + 64;
    float* sF0 = sm[warp] + 256;
    float* sF1 = sm[warp] + 320;
    float* sMS = sm[warp] + 512;
    float* sG  = sm[warp] + 576;
    float* sMV = sm[warp] + 640;

    int c0 = lane, c1 = lane + 32;
    float za = g_z[n * 8 + (lane >> 3)];
    float zb = g_z[n * 8 + 4 + (lane >> 3)];
    float rza = za > 0.f ? 1.f / za : 0.f;
    float rzb = zb > 0.f ? 1.f / zb : 0.f;
    sA0[c0] = g_agg0[n * 64 + c0] * rza;
    sA0[c1] = g_agg0[n * 64 + c1] * rzb;
#pragma unroll
    for (int i = 0; i < 3; i++) {
        sA1[c0 * 3 + i] = g_agg1[n * 192 + i * 64 + c0] * rza;
        sA1[c1 * 3 + i] = g_agg1[n * 192 + i * 64 + c1] * rzb;
    }
    sF0[c0] = g_f0[n * 64 + c0];
    sF0[c1] = g_f0[n * 64 + c1];
#pragma unroll
    for (int i = 0; i < 3; i++) {
        sF1[c0 * 3 + i] = g_f1[n * 192 + i * 64 + c0];
        sF1[c1 * 3 + i] = g_f1[n * 192 + i * 64 + c1];
    }
    __syncwarp();

    float f0a = sF0[c0], f0b = sF0[c1];
    float f1a[3] = {sF1[c0 * 3], sF1[c0 * 3 + 1], sF1[c0 * 3 + 2]};
    float f1b[3] = {sF1[c1 * 3], sF1[c1 * 3 + 1], sF1[c1 * 3 + 2]};
#pragma unroll 4
    for (int c = 0; c < 64; c++) {
        float r = sA0[c];
        f0a += r * P0[c * 64 + c0];
        f0b += r * P0[c * 64 + c1];
        float wa = P1[c * 64 + c0], wbv = P1[c * 64 + c1];
#pragma unroll
        for (int i = 0; i < 3; i++) {
            f1a[i] += sA1[c * 3 + i] * wa;
            f1b[i] += sA1[c * 3 + i] * wbv;
        }
    }
    __syncwarp();
    sF0[c0] = f0a; sF0[c1] = f0b;
#pragma unroll
    for (int i = 0; i < 3; i++) { sF1[c0 * 3 + i] = f1a[i]; sF1[c1 * 3 + i] = f1b[i]; }
    __syncwarp();

    float hs0 = b1s[c0], hs1 = b1s[c1], hs2 = b1s[64 + c0], hs3 = b1s[64 + c1];
#pragma unroll 4
    for (int c = 0; c < 64; c++) {
        float r = sF0[c];
        hs0 += r * W1s[c * 128 + c0];
        hs1 += r * W1s[c * 128 + c1];
        hs2 += r * W1s[c * 128 + 64 + c0];
        hs3 += r * W1s[c * 128 + 64 + c1];
    }
    sMS[c0] = siluf(hs0); sMS[c1] = siluf(hs1);
    sG[c0] = sigf(hs2);   sG[c1] = sigf(hs3);
    __syncwarp();

    float mva[3] = {0, 0, 0}, mvb[3] = {0, 0, 0};
#pragma unroll 4
    for (int c = 0; c < 64; c++) {
        float wa = W1v[c * 64 + c0], wbv = W1v[c * 64 + c1];
#pragma unroll
        for (int i = 0; i < 3; i++) {
            mva[i] += sF1[c * 3 + i] * wa;
            mvb[i] += sF1[c * 3 + i] * wbv;
        }
    }
    float ga = sG[c0], gb = sG[c1];
#pragma unroll
    for (int i = 0; i < 3; i++) { sMV[c0 * 3 + i] = mva[i] * ga; sMV[c1 * 3 + i] = mvb[i] * gb; }
    __syncwarp();

    float o0a = sF0[c0] + b2s[c0], o0b = sF0[c1] + b2s[c1];
    float o1a[3] = {sF1[c0 * 3], sF1[c0 * 3 + 1], sF1[c0 * 3 + 2]};
    float o1b[3] = {sF1[c1 * 3], sF1[c1 * 3 + 1], sF1[c1 * 3 + 2]};
#pragma unroll 4
    for (int c = 0; c < 64; c++) {
        float r = sMS[c];
        o0a += r * W2s[c * 64 + c0];
        o0b += r * W2s[c * 64 + c1];
        float wa = W2v[c * 64 + c0], wbv = W2v[c * 64 + c1];
#pragma unroll
        for (int i = 0; i < 3; i++) {
            o1a[i] += sMV[c * 3 + i] * wa;
            o1b[i] += sMV[c * 3 + i] * wbv;
        }
    }

    long long ob = (long long)n * 256;
    out[ob + c0] = o0a;
    out[ob + c1] = o0b;
#pragma unroll
    for (int i = 0; i < 3; i++) {
        out[ob + 64 + c0 * 3 + i] = o1a[i];
        out[ob + 64 + c1 * 3 + i] = o1b[i];
    }
}

// ---------------- launch ----------------
extern "C" void kernel_launch(void* const* d_in, const int* in_sizes, int n_in,
                              void* d_out, int out_size) {
    const float* pos       = (const float*)d_in[0];
    const float* embed_W   = (const float*)d_in[1];
    const float* exp_w     = (const float*)d_in[2];
    const float* rad_W1    = (const float*)d_in[3];
    const float* rad_b1    = (const float*)d_in[4];
    const float* rad_W2    = (const float*)d_in[5];
    const float* rad_b2    = (const float*)d_in[6];
    const float* rad_Wdeg  = (const float*)d_in[7];
    const float* rad_bdeg  = (const float*)d_in[8];
    const float* rad_Wattn = (const float*)d_in[9];
    const float* rad_battn = (const float*)d_in[10];
    const float* deg_proj0 = (const float*)d_in[11];
    const float* deg_proj1 = (const float*)d_in[12];
    const float* alpha_dot = (const float*)d_in[13];
    const float* out_proj0 = (const float*)d_in[14];
    const float* out_proj1 = (const float*)d_in[15];
    const float* ffn_W1s   = (const float*)d_in[16];
    const float* ffn_b1s   = (const float*)d_in[17];
    const float* ffn_W1v   = (const float*)d_in[18];
    const float* ffn_W2s   = (const float*)d_in[19];
    const float* ffn_b2s   = (const float*)d_in[20];
    const float* ffn_W2v   = (const float*)d_in[21];
    const int* node_atom   = (const int*)d_in[22];
    const int* edge_src    = (const int*)d_in[23];
    const int* edge_dst    = (const int*)d_in[24];
    float* out = (float*)d_out;

    cudaFuncSetAttribute(k1_edge, cudaFuncAttributeMaxDynamicSharedMemorySize, K1_SMEM);

    k0_init<<<1024, 256>>>(embed_W, node_atom);
    k1_edge<<<K1_GRID, 256, K1_SMEM>>>(pos, exp_w, rad_W1, rad_b1, rad_W2, rad_b2,
                                       rad_Wdeg, rad_bdeg, rad_Wattn, rad_battn,
                                       deg_proj0, deg_proj1, edge_src, edge_dst);
    k2_msg<<<NE / 8, 256>>>(pos, alpha_dot, edge_src, edge_dst);
    k3_agg<<<NE / 8, 256>>>(edge_dst);
    k4_node<<<NN / 8, 256>>>(out_proj0, out_proj1, ffn_W1s, ffn_b1s,
                             ffn_W1v, ffn_W2s, ffn_b2s, ffn_W2v, out);
}

// round 7
// speedup vs baseline: 1.3748x; 1.3748x over previous
#include <cuda_runtime.h>
#include <cuda_fp16.h>
#include <math.h>
#include <stdint.h>

#define NN 50000
#define NE 800000
#define LDS_S 66

// ---------------- scratch (device globals) ----------------
__device__ float g_f0[NN * 64];
__device__ float g_f1[NN * 192];          // [n][3][64]
__device__ float g_agg0[NN * 64];
__device__ float g_agg1[NN * 192];        // [n][3][64]
__device__ float g_z[NN * 8];
__device__ unsigned int g_amax[NN * 8];
__device__ __half g_wattn_h[256000000];   // E*320
__device__ __half g_msg0_h[51200000];     // E*64
__device__ __half g_msg1_h[153600000];    // E*192, [e][comp][64]
__device__ float g_a[6400000];            // E*8

typedef unsigned long long u64;

// ---------------- helpers ----------------
__device__ __forceinline__ float siluf(float x) { return __fdividef(x, 1.f + __expf(-x)); }
__device__ __forceinline__ float sigf(float x) { return __fdividef(1.f, 1.f + __expf(-x)); }

__device__ __forceinline__ unsigned int encf(float f) {
    unsigned int u = __float_as_uint(f);
    return (u & 0x80000000u) ? ~u : (u | 0x80000000u);
}
__device__ __forceinline__ float decf(unsigned int u) {
    return (u & 0x80000000u) ? __uint_as_float(u ^ 0x80000000u) : __uint_as_float(~u);
}

// packed f32x2 ops
__device__ __forceinline__ u64 pk(float x) {
    u64 r; asm("mov.b64 %0, {%1, %1};" : "=l"(r) : "f"(x)); return r;
}
__device__ __forceinline__ void fma2(u64& d, u64 a, u64 b) {
    asm("fma.rn.f32x2 %0, %1, %2, %0;" : "+l"(d) : "l"(a), "l"(b));
}
__device__ __forceinline__ float2 up(u64 a) {
    float2 v; asm("mov.b64 {%0, %1}, %2;" : "=f"(v.x), "=f"(v.y) : "l"(a)); return v;
}

// vector reduction atomics (sm_90+)
__device__ __forceinline__ void red_v2(float* p, float a, float b) {
    asm volatile("{ .reg .u64 q; cvta.to.global.u64 q, %0; red.global.add.v2.f32 [q], {%1, %2}; }"
                 :: "l"(p), "f"(a), "f"(b) : "memory");
}
__device__ __forceinline__ void red_v4(float* p, float a, float b, float c, float d) {
    asm volatile("{ .reg .u64 q; cvta.to.global.u64 q, %0; red.global.add.v4.f32 [q], {%1, %2, %3, %4}; }"
                 :: "l"(p), "f"(a), "f"(b), "f"(c), "f"(d) : "memory");
}

// ---------------- K0: init node state ----------------
__global__ void k0_init(const float* __restrict__ embed_W, const int* __restrict__ node_atom) {
    int stride = gridDim.x * blockDim.x;
    for (int i = blockIdx.x * blockDim.x + threadIdx.x; i < NN * 192; i += stride) {
        g_f1[i] = 0.f;
        g_agg1[i] = 0.f;
        if (i < NN * 64) {
            int n = i >> 6, c = i & 63;
            g_f0[i] = embed_W[node_atom[n] * 64 + c];
            g_agg0[i] = 0.f;
        }
        if (i < NN * 8) {
            g_amax[i] = 0x007FFFFFu;
            g_z[i] = 0.f;
        }
    }
}

// ---------------- k-major GEMM core with f32x2 ----------------
__device__ __forceinline__ void gemm_t(const float* __restrict__ As, int eA,
                                       const float* __restrict__ Bg, int ldb,
                                       int colbase, int c4, int K,
                                       u64 acc[4][4]) {
#pragma unroll
    for (int p = 0; p < 4; p++)
#pragma unroll
        for (int j = 0; j < 4; j++) acc[p][j] = 0ull;
    const float* Bp = Bg + colbase + c4;
#pragma unroll 4
    for (int k = 0; k < K; k++) {
        const u64* ap = reinterpret_cast<const u64*>(As + k * LDS_S + eA);
        u64 a0 = ap[0], a1 = ap[1], a2 = ap[2], a3 = ap[3];
        float4 b = *reinterpret_cast<const float4*>(Bp + k * ldb);
        u64 bx = pk(b.x), by = pk(b.y), bz = pk(b.z), bw = pk(b.w);
        fma2(acc[0][0], a0, bx); fma2(acc[0][1], a0, by); fma2(acc[0][2], a0, bz); fma2(acc[0][3], a0, bw);
        fma2(acc[1][0], a1, bx); fma2(acc[1][1], a1, by); fma2(acc[1][2], a1, bz); fma2(acc[1][3], a1, bw);
        fma2(acc[2][0], a2, bx); fma2(acc[2][1], a2, by); fma2(acc[2][2], a2, bz); fma2(acc[2][3], a2, bw);
        fma2(acc[3][0], a3, bx); fma2(acc[3][1], a3, by); fma2(acc[3][2], a3, bz); fma2(acc[3][3], a3, bw);
    }
}

// ---------------- K1: edge-tiled radial MLP + degree scatter + w_attn ----------------
__global__ void __launch_bounds__(128) k1_edge(
    const float* __restrict__ pos, const float* __restrict__ exp_w,
    const float* __restrict__ W1, const float* __restrict__ b1,
    const float* __restrict__ W2, const float* __restrict__ b2,
    const float* __restrict__ Wdeg, const float* __restrict__ bdeg,
    const float* __restrict__ Wattn, const float* __restrict__ battn,
    const float* __restrict__ P0, const float* __restrict__ P1,
    const int* __restrict__ esrc, const int* __restrict__ edst)
{
    __shared__ float SA[64 * LDS_S];
    __shared__ float SB[64 * LDS_S];
    __shared__ float sy[3][64];
    __shared__ int sdst[64];
    __shared__ float stmp[2][64];

    int tid = threadIdx.x;
    int cg = tid & 15, c4 = cg << 2;
    int eg = tid >> 4, eA = eg << 3;       // 8 edges per thread (4 pairs)
    int ebase = blockIdx.x * 64;

    // geometry (threads 0..63)
    if (tid < 64) {
        int e = ebase + tid;
        int s = esrc[e], d = edst[e];
        float vx = pos[d * 3 + 0] - pos[s * 3 + 0];
        float vy = pos[d * 3 + 1] - pos[s * 3 + 1];
        float vz = pos[d * 3 + 2] - pos[s * 3 + 2];
        float dist = sqrtf(vx * vx + vy * vy + vz * vz + 1e-9f);
        float ri = 1.f / dist;
        const float PI_ = 3.14159265358979323846f;
        float cut = (dist < 5.0f) ? 0.5f * (__cosf(PI_ * dist * 0.2f) + 1.f) : 0.f;
        sdst[tid] = d;
        sy[0][tid] = vx * ri; sy[1][tid] = vy * ri; sy[2][tid] = vz * ri;
        stmp[0][tid] = cut;
        stmp[1][tid] = __expf(-dist);
    }
    __syncthreads();

    // RBF into SA[k][e]
    {
        const float START = 0.006737946999085467f;
        const float STEP = (1.0f - START) / 49.0f;
        const float BETA = 1.0f / ((0.04f * (1.0f - START)) * (0.04f * (1.0f - START)));
        int er = tid & 63, k0 = tid >> 6;
        float cut = stmp[0][er], expd = stmp[1][er];
        for (int k = k0; k < 50; k += 2) {
            float t = expd - (START + (float)k * STEP);
            SA[k * LDS_S + er] = cut * __expf(-BETA * t * t);
        }
    }
    __syncthreads();

    u64 acc[4][4];

    // GEMM1: rbf(50) -> 64, silu -> SB
    gemm_t(SA, eA, W1, 64, 0, c4, 50, acc);
    {
#pragma unroll
        for (int j = 0; j < 4; j++) {
            float bb = b1[c4 + j];
#pragma unroll
            for (int p = 0; p < 4; p++) {
                float2 v = up(acc[p][j]);
                v.x = siluf(v.x + bb); v.y = siluf(v.y + bb);
                *reinterpret_cast<float2*>(&SB[(c4 + j) * LDS_S + eA + 2 * p]) = v;
            }
        }
    }
    __syncthreads();

    // GEMM2: 64 -> 64, silu -> SA (h2)
    gemm_t(SB, eA, W2, 64, 0, c4, 64, acc);
    {
#pragma unroll
        for (int j = 0; j < 4; j++) {
            float bb = b2[c4 + j];
#pragma unroll
            for (int p = 0; p < 4; p++) {
                float2 v = up(acc[p][j]);
                v.x = siluf(v.x + bb); v.y = siluf(v.y + bb);
                *reinterpret_cast<float2*>(&SA[(c4 + j) * LDS_S + eA + 2 * p]) = v;
            }
        }
    }
    __syncthreads();

    // GEMM5: w_attn = h2 @ Wattn (5 chunks) -> fp16 global
    for (int ch = 0; ch < 5; ch++) {
        gemm_t(SA, eA, Wattn, 320, ch * 64, c4, 64, acc);
        int col = ch * 64 + c4;
        float b0v = battn[col], b1v = battn[col + 1], b2v = battn[col + 2], b3v = battn[col + 3];
#pragma unroll
        for (int p = 0; p < 4; p++) {
            float2 v0 = up(acc[p][0]), v1 = up(acc[p][1]), v2 = up(acc[p][2]), v3 = up(acc[p][3]);
            long long wbA = (long long)(ebase + eA + 2 * p) * 320 + col;
            long long wbB = wbA + 320;
            *reinterpret_cast<__half2*>(&g_wattn_h[wbA])     = __floats2half2_rn(v0.x + b0v, v1.x + b1v);
            *reinterpret_cast<__half2*>(&g_wattn_h[wbA + 2]) = __floats2half2_rn(v2.x + b2v, v3.x + b3v);
            *reinterpret_cast<__half2*>(&g_wattn_h[wbB])     = __floats2half2_rn(v0.y + b0v, v1.y + b1v);
            *reinterpret_cast<__half2*>(&g_wattn_h[wbB + 2]) = __floats2half2_rn(v2.y + b2v, v3.y + b3v);
        }
    }

    const float INV = 0.25f;  // 1/sqrt(AVG_DEG)

    // GEMM3a: e0 -> SB
    gemm_t(SA, eA, Wdeg, 128, 0, c4, 64, acc);
    {
#pragma unroll
        for (int j = 0; j < 4; j++) {
            float bb = bdeg[c4 + j], ee = exp_w[c4 + j];
#pragma unroll
            for (int p = 0; p < 4; p++) {
                float2 v = up(acc[p][j]);
                v.x = (v.x + bb) * ee; v.y = (v.y + bb) * ee;
                *reinterpret_cast<float2*>(&SB[(c4 + j) * LDS_S + eA + 2 * p]) = v;
            }
        }
    }
    __syncthreads();

    // GEMM4a: e0 @ P0 -> red.v4 scatter to f0
    gemm_t(SB, eA, P0, 64, 0, c4, 64, acc);
#pragma unroll
    for (int p = 0; p < 4; p++) {
        int dA = sdst[eA + 2 * p], dB = sdst[eA + 2 * p + 1];
        float2 v0 = up(acc[p][0]), v1 = up(acc[p][1]), v2 = up(acc[p][2]), v3 = up(acc[p][3]);
        red_v4(&g_f0[dA * 64 + c4], INV * v0.x, INV * v1.x, INV * v2.x, INV * v3.x);
        red_v4(&g_f0[dB * 64 + c4], INV * v0.y, INV * v1.y, INV * v2.y, INV * v3.y);
    }
    __syncthreads();

    // GEMM3b: e1 -> SB
    gemm_t(SA, eA, Wdeg, 128, 64, c4, 64, acc);
    {
#pragma unroll
        for (int j = 0; j < 4; j++) {
            float bb = bdeg[64 + c4 + j], ee = exp_w[c4 + j];
#pragma unroll
            for (int p = 0; p < 4; p++) {
                float2 v = up(acc[p][j]);
                v.x = (v.x + bb) * ee; v.y = (v.y + bb) * ee;
                *reinterpret_cast<float2*>(&SB[(c4 + j) * LDS_S + eA + 2 * p]) = v;
            }
        }
    }
    __syncthreads();

    // GEMM4b: e1 @ P1, times Y -> red.v4 scatter to f1 ([n][3][64])
    gemm_t(SB, eA, P1, 64, 0, c4, 64, acc);
#pragma unroll
    for (int p = 0; p < 4; p++) {
        float2 v0 = up(acc[p][0]), v1 = up(acc[p][1]), v2 = up(acc[p][2]), v3 = up(acc[p][3]);
#pragma unroll
        for (int half = 0; half < 2; half++) {
            int el = eA + 2 * p + half;
            int d = sdst[el];
            float a0 = INV * (half ? v0.y : v0.x);
            float a1 = INV * (half ? v1.y : v1.x);
            float a2 = INV * (half ? v2.y : v2.x);
            float a3 = INV * (half ? v3.y : v3.x);
            float* pp = &g_f1[d * 192];
#pragma unroll
            for (int i = 0; i < 3; i++) {
                float yy = sy[i][el];
                red_v4(pp + i * 64 + c4, a0 * yy, a1 * yy, a2 * yy, a3 * yy);
            }
        }
    }
}

// ---------------- K2: messages + logits + segment max ----------------
__global__ void __launch_bounds__(256) k2_msg(
    const float* __restrict__ pos, const float* __restrict__ alpha_dot,
    const int* __restrict__ esrc, const int* __restrict__ edst)
{
    int warp = threadIdx.x >> 5, lane = threadIdx.x & 31;
    int e = blockIdx.x * 8 + warp;
    if (e >= NE) return;
    int s = esrc[e], d = edst[e];
    float vx = pos[d * 3 + 0] - pos[s * 3 + 0];
    float vy = pos[d * 3 + 1] - pos[s * 3 + 1];
    float vz = pos[d * 3 + 2] - pos[s * 3 + 2];
    float ri = rsqrtf(vx * vx + vy * vy + vz * vz + 1e-9f);
    float y0 = vx * ri, y1 = vy * ri, y2 = vz * ri;

    int c0 = lane, c1 = lane + 32;
    float s0a = g_f0[s * 64 + c0], s0b = g_f0[s * 64 + c1];
    const float* f1p = &g_f1[s * 192];
    float sa0 = f1p[0 * 64 + c0], sa1 = f1p[1 * 64 + c0], sa2 = f1p[2 * 64 + c0];
    float sb0 = f1p[0 * 64 + c1], sb1 = f1p[1 * 64 + c1], sb2 = f1p[2 * 64 + c1];

    long long wb = (long long)e * 320;
    float w0a = __half2float(g_wattn_h[wb + c0]),       w0b = __half2float(g_wattn_h[wb + c1]);
    float w1a = __half2float(g_wattn_h[wb + 64 + c0]),  w1b = __half2float(g_wattn_h[wb + 64 + c1]);
    float w2a = __half2float(g_wattn_h[wb + 128 + c0]), w2b = __half2float(g_wattn_h[wb + 128 + c1]);
    float w3a = __half2float(g_wattn_h[wb + 192 + c0]), w3b = __half2float(g_wattn_h[wb + 192 + c1]);
    float w4a = __half2float(g_wattn_h[wb + 256 + c0]), w4b = __half2float(g_wattn_h[wb + 256 + c1]);

    const float IS3 = 0.57735026918962576f;
    const float IS2 = 0.70710678118654752f;

    float dva = sa0 * y0 + sa1 * y1 + sa2 * y2;
    float dvb = sb0 * y0 + sb1 * y1 + sb2 * y2;
    float m0a = w0a * s0a + w3a * dva * IS3;
    float m0b = w0b * s0b + w3b * dvb * IS3;

    float cxa0 = sa1 * y2 - sa2 * y1, cxa1 = sa2 * y0 - sa0 * y2, cxa2 = sa0 * y1 - sa1 * y0;
    float cxb0 = sb1 * y2 - sb2 * y1, cxb1 = sb2 * y0 - sb0 * y2, cxb2 = sb0 * y1 - sb1 * y0;
    float w1sa = w1a * s0a, w1sb = w1b * s0b;
    float m1a0 = w1sa * y0 + w2a * sa0 + w4a * cxa0 * IS2;
    float m1a1 = w1sa * y1 + w2a * sa1 + w4a * cxa1 * IS2;
    float m1a2 = w1sa * y2 + w2a * sa2 + w4a * cxa2 * IS2;
    float m1b0 = w1sb * y0 + w2b * sb0 + w4b * cxb0 * IS2;
    float m1b1 = w1sb * y1 + w2b * sb1 + w4b * cxb1 * IS2;
    float m1b2 = w1sb * y2 + w2b * sb2 + w4b * cxb2 * IS2;

    long long mb0 = (long long)e * 64, mb1 = (long long)e * 192;
    g_msg0_h[mb0 + c0] = __float2half(m0a);
    g_msg0_h[mb0 + c1] = __float2half(m0b);
    g_msg1_h[mb1 + 0 * 64 + c0] = __float2half(m1a0);
    g_msg1_h[mb1 + 1 * 64 + c0] = __float2half(m1a1);
    g_msg1_h[mb1 + 2 * 64 + c0] = __float2half(m1a2);
    g_msg1_h[mb1 + 0 * 64 + c1] = __float2half(m1b0);
    g_msg1_h[mb1 + 1 * 64 + c1] = __float2half(m1b1);
    g_msg1_h[mb1 + 2 * 64 + c1] = __float2half(m1b2);

    float slra = 0.2f * m0a + 0.8f * m0a * sigf(m0a);
    float slrb = 0.2f * m0b + 0.8f * m0b * sigf(m0b);
    float pa = slra * alpha_dot[c0];
    float pb = slrb * alpha_dot[c1];
#pragma unroll
    for (int off = 4; off; off >>= 1) {
        pa += __shfl_xor_sync(0xffffffffu, pa, off);
        pb += __shfl_xor_sync(0xffffffffu, pb, off);
    }
    if ((lane & 7) == 0) {
        int h0 = lane >> 3;
        g_a[(long long)e * 8 + h0] = pa;
        g_a[(long long)e * 8 + h0 + 4] = pb;
        atomicMax(&g_amax[d * 8 + h0], encf(pa));
        atomicMax(&g_amax[d * 8 + h0 + 4], encf(pb));
    }
}

// ---------------- K3: exp + fused (z, ea*msg) scatter (1 head / thread) ----------------
__global__ void __launch_bounds__(256) k3_agg(const int* __restrict__ edst) {
    int warp = threadIdx.x >> 5, lane = threadIdx.x & 31;
    int e = blockIdx.x * 8 + warp;
    if (e >= NE) return;
    int d = edst[e];
    int h = lane >> 2;                 // head 0..7 (4 lanes per head)
    float aa = g_a[(long long)e * 8 + h];
    float ma = decf(g_amax[d * 8 + h]);
    float ea = __expf(aa - ma);
    if ((lane & 3) == 0) atomicAdd(&g_z[d * 8 + h], ea);

    int c = lane << 1;                 // channels c, c+1 (same head)
    long long mb0 = (long long)e * 64 + c, mb1 = (long long)e * 192 + c;
    float2 v0 = __half22float2(*reinterpret_cast<const __half2*>(&g_msg0_h[mb0]));
    red_v2(&g_agg0[d * 64 + c], ea * v0.x, ea * v0.y);
#pragma unroll
    for (int i = 0; i < 3; i++) {
        float2 v = __half22float2(*reinterpret_cast<const __half2*>(&g_msg1_h[mb1 + i * 64]));
        red_v2(&g_agg1[d * 192 + i * 64 + c], ea * v.x, ea * v.y);
    }
}

// ---------------- K4: node update ----------------
__global__ void __launch_bounds__(256) k4_node(
    const float* __restrict__ P0, const float* __restrict__ P1,
    const float* __restrict__ W1s, const float* __restrict__ b1s,
    const float* __restrict__ W1v, const float* __restrict__ W2s,
    const float* __restrict__ b2s, const float* __restrict__ W2v,
    float* __restrict__ out)
{
    __shared__ float sm[8][832];
    int warp = threadIdx.x >> 5, lane = threadIdx.x & 31;
    int n = blockIdx.x * 8 + warp;
    if (n >= NN) return;
    float* sA0 = sm[warp];
    float* sA1 = sm[warp] + 64;
    float* sF0 = sm[warp] + 256;
    float* sF1 = sm[warp] + 320;
    float* sMS = sm[warp] + 512;
    float* sG  = sm[warp] + 576;
    float* sMV = sm[warp] + 640;

    int c0 = lane, c1 = lane + 32;
    float za = g_z[n * 8 + (lane >> 3)];
    float zb = g_z[n * 8 + 4 + (lane >> 3)];
    float rza = za > 0.f ? 1.f / za : 0.f;
    float rzb = zb > 0.f ? 1.f / zb : 0.f;
    sA0[c0] = g_agg0[n * 64 + c0] * rza;
    sA0[c1] = g_agg0[n * 64 + c1] * rzb;
#pragma unroll
    for (int i = 0; i < 3; i++) {
        sA1[c0 * 3 + i] = g_agg1[n * 192 + i * 64 + c0] * rza;
        sA1[c1 * 3 + i] = g_agg1[n * 192 + i * 64 + c1] * rzb;
    }
    sF0[c0] = g_f0[n * 64 + c0];
    sF0[c1] = g_f0[n * 64 + c1];
#pragma unroll
    for (int i = 0; i < 3; i++) {
        sF1[c0 * 3 + i] = g_f1[n * 192 + i * 64 + c0];
        sF1[c1 * 3 + i] = g_f1[n * 192 + i * 64 + c1];
    }
    __syncwarp();

    float f0a = sF0[c0], f0b = sF0[c1];
    float f1a[3] = {sF1[c0 * 3], sF1[c0 * 3 + 1], sF1[c0 * 3 + 2]};
    float f1b[3] = {sF1[c1 * 3], sF1[c1 * 3 + 1], sF1[c1 * 3 + 2]};
#pragma unroll 4
    for (int c = 0; c < 64; c++) {
        float r = sA0[c];
        f0a += r * P0[c * 64 + c0];
        f0b += r * P0[c * 64 + c1];
        float wa = P1[c * 64 + c0], wbv = P1[c * 64 + c1];
#pragma unroll
        for (int i = 0; i < 3; i++) {
            f1a[i] += sA1[c * 3 + i] * wa;
            f1b[i] += sA1[c * 3 + i] * wbv;
        }
    }
    __syncwarp();
    sF0[c0] = f0a; sF0[c1] = f0b;
#pragma unroll
    for (int i = 0; i < 3; i++) { sF1[c0 * 3 + i] = f1a[i]; sF1[c1 * 3 + i] = f1b[i]; }
    __syncwarp();

    float hs0 = b1s[c0], hs1 = b1s[c1], hs2 = b1s[64 + c0], hs3 = b1s[64 + c1];
#pragma unroll 4
    for (int c = 0; c < 64; c++) {
        float r = sF0[c];
        hs0 += r * W1s[c * 128 + c0];
        hs1 += r * W1s[c * 128 + c1];
        hs2 += r * W1s[c * 128 + 64 + c0];
        hs3 += r * W1s[c * 128 + 64 + c1];
    }
    sMS[c0] = siluf(hs0); sMS[c1] = siluf(hs1);
    sG[c0] = sigf(hs2);   sG[c1] = sigf(hs3);
    __syncwarp();

    float mva[3] = {0, 0, 0}, mvb[3] = {0, 0, 0};
#pragma unroll 4
    for (int c = 0; c < 64; c++) {
        float wa = W1v[c * 64 + c0], wbv = W1v[c * 64 + c1];
#pragma unroll
        for (int i = 0; i < 3; i++) {
            mva[i] += sF1[c * 3 + i] * wa;
            mvb[i] += sF1[c * 3 + i] * wbv;
        }
    }
    float ga = sG[c0], gb = sG[c1];
#pragma unroll
    for (int i = 0; i < 3; i++) { sMV[c0 * 3 + i] = mva[i] * ga; sMV[c1 * 3 + i] = mvb[i] * gb; }
    __syncwarp();

    float o0a = sF0[c0] + b2s[c0], o0b = sF0[c1] + b2s[c1];
    float o1a[3] = {sF1[c0 * 3], sF1[c0 * 3 + 1], sF1[c0 * 3 + 2]};
    float o1b[3] = {sF1[c1 * 3], sF1[c1 * 3 + 1], sF1[c1 * 3 + 2]};
#pragma unroll 4
    for (int c = 0; c < 64; c++) {
        float r = sMS[c];
        o0a += r * W2s[c * 64 + c0];
        o0b += r * W2s[c * 64 + c1];
        float wa = W2v[c * 64 + c0], wbv = W2v[c * 64 + c1];
#pragma unroll
        for (int i = 0; i < 3; i++) {
            o1a[i] += sMV[c * 3 + i] * wa;
            o1b[i] += sMV[c * 3 + i] * wbv;
        }
    }

    long long ob = (long long)n * 256;
    out[ob + c0] = o0a;
    out[ob + c1] = o0b;
#pragma unroll
    for (int i = 0; i < 3; i++) {
        out[ob + 64 + c0 * 3 + i] = o1a[i];
        out[ob + 64 + c1 * 3 + i] = o1b[i];
    }
}

// ---------------- launch ----------------
extern "C" void kernel_launch(void* const* d_in, const int* in_sizes, int n_in,
                              void* d_out, int out_size) {
    const float* pos       = (const float*)d_in[0];
    const float* embed_W   = (const float*)d_in[1];
    const float* exp_w     = (const float*)d_in[2];
    const float* rad_W1    = (const float*)d_in[3];
    const float* rad_b1    = (const float*)d_in[4];
    const float* rad_W2    = (const float*)d_in[5];
    const float* rad_b2    = (const float*)d_in[6];
    const float* rad_Wdeg  = (const float*)d_in[7];
    const float* rad_bdeg  = (const float*)d_in[8];
    const float* rad_Wattn = (const float*)d_in[9];
    const float* rad_battn = (const float*)d_in[10];
    const float* deg_proj0 = (const float*)d_in[11];
    const float* deg_proj1 = (const float*)d_in[12];
    const float* alpha_dot = (const float*)d_in[13];
    const float* out_proj0 = (const float*)d_in[14];
    const float* out_proj1 = (const float*)d_in[15];
    const float* ffn_W1s   = (const float*)d_in[16];
    const float* ffn_b1s   = (const float*)d_in[17];
    const float* ffn_W1v   = (const float*)d_in[18];
    const float* ffn_W2s   = (const float*)d_in[19];
    const float* ffn_b2s   = (const float*)d_in[20];
    const float* ffn_W2v   = (const float*)d_in[21];
    const int* node_atom   = (const int*)d_in[22];
    const int* edge_src    = (const int*)d_in[23];
    const int* edge_dst    = (const int*)d_in[24];
    float* out = (float*)d_out;

    k0_init<<<1024, 256>>>(embed_W, node_atom);
    k1_edge<<<NE / 64, 128>>>(pos, exp_w, rad_W1, rad_b1, rad_W2, rad_b2,
                              rad_Wdeg, rad_bdeg, rad_Wattn, rad_battn,
                              deg_proj0, deg_proj1, edge_src, edge_dst);
    k2_msg<<<NE / 8, 256>>>(pos, alpha_dot, edge_src, edge_dst);
    k3_agg<<<NE / 8, 256>>>(edge_dst);
    k4_node<<<NN / 8, 256>>>(out_proj0, out_proj1, ffn_W1s, ffn_b1s,
                             ffn_W1v, ffn_W2s, ffn_b2s, ffn_W2v, out);
}

// round 8
// speedup vs baseline: 1.5824x; 1.1510x over previous
#include <cuda_runtime.h>
#include <cuda_fp16.h>
#include <math.h>
#include <stdint.h>

#define NN 50000
#define NE 800000
#define LDS_S 66

// ---------------- scratch (device globals) ----------------
__device__ float g_f0[NN * 64];
__device__ float g_f1[NN * 192];          // [n][3][64]
__device__ float g_agg0[NN * 64];
__device__ float g_agg1[NN * 192];        // [n][3][64]
__device__ float g_z[NN * 8];
__device__ __half g_wattn_h[256000000];   // E*320

typedef unsigned long long u64;

// ---------------- helpers ----------------
__device__ __forceinline__ float siluf(float x) { return __fdividef(x, 1.f + __expf(-x)); }
__device__ __forceinline__ float sigf(float x) { return __fdividef(1.f, 1.f + __expf(-x)); }

// packed f32x2 ops
__device__ __forceinline__ u64 pk(float x) {
    u64 r; asm("mov.b64 %0, {%1, %1};" : "=l"(r) : "f"(x)); return r;
}
__device__ __forceinline__ void fma2(u64& d, u64 a, u64 b) {
    asm("fma.rn.f32x2 %0, %1, %2, %0;" : "+l"(d) : "l"(a), "l"(b));
}
__device__ __forceinline__ float2 up(u64 a) {
    float2 v; asm("mov.b64 {%0, %1}, %2;" : "=f"(v.x), "=f"(v.y) : "l"(a)); return v;
}

// vector reduction atomics (sm_90+)
__device__ __forceinline__ void red_v2(float* p, float a, float b) {
    asm volatile("{ .reg .u64 q; cvta.to.global.u64 q, %0; red.global.add.v2.f32 [q], {%1, %2}; }"
                 :: "l"(p), "f"(a), "f"(b) : "memory");
}
__device__ __forceinline__ void red_v4(float* p, float a, float b, float c, float d) {
    asm volatile("{ .reg .u64 q; cvta.to.global.u64 q, %0; red.global.add.v4.f32 [q], {%1, %2, %3, %4}; }"
                 :: "l"(p), "f"(a), "f"(b), "f"(c), "f"(d) : "memory");
}

// ---------------- K0: init node state ----------------
__global__ void k0_init(const float* __restrict__ embed_W, const int* __restrict__ node_atom) {
    int stride = gridDim.x * blockDim.x;
    for (int i = blockIdx.x * blockDim.x + threadIdx.x; i < NN * 192; i += stride) {
        g_f1[i] = 0.f;
        g_agg1[i] = 0.f;
        if (i < NN * 64) {
            int n = i >> 6, c = i & 63;
            g_f0[i] = embed_W[node_atom[n] * 64 + c];
            g_agg0[i] = 0.f;
        }
        if (i < NN * 8) g_z[i] = 0.f;
    }
}

// ---------------- k-major GEMM core with f32x2 ----------------
__device__ __forceinline__ void gemm_t(const float* __restrict__ As, int eA,
                                       const float* __restrict__ Bg, int ldb,
                                       int colbase, int c4, int K,
                                       u64 acc[4][4]) {
#pragma unroll
    for (int p = 0; p < 4; p++)
#pragma unroll
        for (int j = 0; j < 4; j++) acc[p][j] = 0ull;
    const float* Bp = Bg + colbase + c4;
#pragma unroll 4
    for (int k = 0; k < K; k++) {
        const u64* ap = reinterpret_cast<const u64*>(As + k * LDS_S + eA);
        u64 a0 = ap[0], a1 = ap[1], a2 = ap[2], a3 = ap[3];
        float4 b = *reinterpret_cast<const float4*>(Bp + k * ldb);
        u64 bx = pk(b.x), by = pk(b.y), bz = pk(b.z), bw = pk(b.w);
        fma2(acc[0][0], a0, bx); fma2(acc[0][1], a0, by); fma2(acc[0][2], a0, bz); fma2(acc[0][3], a0, bw);
        fma2(acc[1][0], a1, bx); fma2(acc[1][1], a1, by); fma2(acc[1][2], a1, bz); fma2(acc[1][3], a1, bw);
        fma2(acc[2][0], a2, bx); fma2(acc[2][1], a2, by); fma2(acc[2][2], a2, bz); fma2(acc[2][3], a2, bw);
        fma2(acc[3][0], a3, bx); fma2(acc[3][1], a3, by); fma2(acc[3][2], a3, bz); fma2(acc[3][3], a3, bw);
    }
}

// ---------------- K1: edge-tiled radial MLP + degree scatter + w_attn ----------------
__global__ void __launch_bounds__(128) k1_edge(
    const float* __restrict__ pos, const float* __restrict__ exp_w,
    const float* __restrict__ W1, const float* __restrict__ b1,
    const float* __restrict__ W2, const float* __restrict__ b2,
    const float* __restrict__ Wdeg, const float* __restrict__ bdeg,
    const float* __restrict__ Wattn, const float* __restrict__ battn,
    const float* __restrict__ P0, const float* __restrict__ P1,
    const int* __restrict__ esrc, const int* __restrict__ edst)
{
    __shared__ float SA[64 * LDS_S];
    __shared__ float SB[64 * LDS_S];
    __shared__ float sy[3][64];
    __shared__ int sdst[64];
    __shared__ float stmp[2][64];

    int tid = threadIdx.x;
    int cg = tid & 15, c4 = cg << 2;
    int eg = tid >> 4, eA = eg << 3;
    int ebase = blockIdx.x * 64;

    if (tid < 64) {
        int e = ebase + tid;
        int s = esrc[e], d = edst[e];
        float vx = pos[d * 3 + 0] - pos[s * 3 + 0];
        float vy = pos[d * 3 + 1] - pos[s * 3 + 1];
        float vz = pos[d * 3 + 2] - pos[s * 3 + 2];
        float dist = sqrtf(vx * vx + vy * vy + vz * vz + 1e-9f);
        float ri = 1.f / dist;
        const float PI_ = 3.14159265358979323846f;
        float cut = (dist < 5.0f) ? 0.5f * (__cosf(PI_ * dist * 0.2f) + 1.f) : 0.f;
        sdst[tid] = d;
        sy[0][tid] = vx * ri; sy[1][tid] = vy * ri; sy[2][tid] = vz * ri;
        stmp[0][tid] = cut;
        stmp[1][tid] = __expf(-dist);
    }
    __syncthreads();

    {
        const float START = 0.006737946999085467f;
        const float STEP = (1.0f - START) / 49.0f;
        const float BETA = 1.0f / ((0.04f * (1.0f - START)) * (0.04f * (1.0f - START)));
        int er = tid & 63, k0 = tid >> 6;
        float cut = stmp[0][er], expd = stmp[1][er];
        for (int k = k0; k < 50; k += 2) {
            float t = expd - (START + (float)k * STEP);
            SA[k * LDS_S + er] = cut * __expf(-BETA * t * t);
        }
    }
    __syncthreads();

    u64 acc[4][4];

    // GEMM1: rbf(50) -> 64, silu -> SB
    gemm_t(SA, eA, W1, 64, 0, c4, 50, acc);
    {
#pragma unroll
        for (int j = 0; j < 4; j++) {
            float bb = b1[c4 + j];
#pragma unroll
            for (int p = 0; p < 4; p++) {
                float2 v = up(acc[p][j]);
                v.x = siluf(v.x + bb); v.y = siluf(v.y + bb);
                *reinterpret_cast<float2*>(&SB[(c4 + j) * LDS_S + eA + 2 * p]) = v;
            }
        }
    }
    __syncthreads();

    // GEMM2: 64 -> 64, silu -> SA (h2)
    gemm_t(SB, eA, W2, 64, 0, c4, 64, acc);
    {
#pragma unroll
        for (int j = 0; j < 4; j++) {
            float bb = b2[c4 + j];
#pragma unroll
            for (int p = 0; p < 4; p++) {
                float2 v = up(acc[p][j]);
                v.x = siluf(v.x + bb); v.y = siluf(v.y + bb);
                *reinterpret_cast<float2*>(&SA[(c4 + j) * LDS_S + eA + 2 * p]) = v;
            }
        }
    }
    __syncthreads();

    // GEMM5: w_attn = h2 @ Wattn (5 chunks) -> fp16 global
    for (int ch = 0; ch < 5; ch++) {
        gemm_t(SA, eA, Wattn, 320, ch * 64, c4, 64, acc);
        int col = ch * 64 + c4;
        float b0v = battn[col], b1v = battn[col + 1], b2v = battn[col + 2], b3v = battn[col + 3];
#pragma unroll
        for (int p = 0; p < 4; p++) {
            float2 v0 = up(acc[p][0]), v1 = up(acc[p][1]), v2 = up(acc[p][2]), v3 = up(acc[p][3]);
            long long wbA = (long long)(ebase + eA + 2 * p) * 320 + col;
            long long wbB = wbA + 320;
            *reinterpret_cast<__half2*>(&g_wattn_h[wbA])     = __floats2half2_rn(v0.x + b0v, v1.x + b1v);
            *reinterpret_cast<__half2*>(&g_wattn_h[wbA + 2]) = __floats2half2_rn(v2.x + b2v, v3.x + b3v);
            *reinterpret_cast<__half2*>(&g_wattn_h[wbB])     = __floats2half2_rn(v0.y + b0v, v1.y + b1v);
            *reinterpret_cast<__half2*>(&g_wattn_h[wbB + 2]) = __floats2half2_rn(v2.y + b2v, v3.y + b3v);
        }
    }

    const float INV = 0.25f;

    // GEMM3a: e0 -> SB
    gemm_t(SA, eA, Wdeg, 128, 0, c4, 64, acc);
    {
#pragma unroll
        for (int j = 0; j < 4; j++) {
            float bb = bdeg[c4 + j], ee = exp_w[c4 + j];
#pragma unroll
            for (int p = 0; p < 4; p++) {
                float2 v = up(acc[p][j]);
                v.x = (v.x + bb) * ee; v.y = (v.y + bb) * ee;
                *reinterpret_cast<float2*>(&SB[(c4 + j) * LDS_S + eA + 2 * p]) = v;
            }
        }
    }
    __syncthreads();

    // GEMM4a: e0 @ P0 -> red.v4 scatter to f0
    gemm_t(SB, eA, P0, 64, 0, c4, 64, acc);
#pragma unroll
    for (int p = 0; p < 4; p++) {
        int dA = sdst[eA + 2 * p], dB = sdst[eA + 2 * p + 1];
        float2 v0 = up(acc[p][0]), v1 = up(acc[p][1]), v2 = up(acc[p][2]), v3 = up(acc[p][3]);
        red_v4(&g_f0[dA * 64 + c4], INV * v0.x, INV * v1.x, INV * v2.x, INV * v3.x);
        red_v4(&g_f0[dB * 64 + c4], INV * v0.y, INV * v1.y, INV * v2.y, INV * v3.y);
    }
    __syncthreads();

    // GEMM3b: e1 -> SB
    gemm_t(SA, eA, Wdeg, 128, 64, c4, 64, acc);
    {
#pragma unroll
        for (int j = 0; j < 4; j++) {
            float bb = bdeg[64 + c4 + j], ee = exp_w[c4 + j];
#pragma unroll
            for (int p = 0; p < 4; p++) {
                float2 v = up(acc[p][j]);
                v.x = (v.x + bb) * ee; v.y = (v.y + bb) * ee;
                *reinterpret_cast<float2*>(&SB[(c4 + j) * LDS_S + eA + 2 * p]) = v;
            }
        }
    }
    __syncthreads();

    // GEMM4b: e1 @ P1, times Y -> red.v4 scatter to f1
    gemm_t(SB, eA, P1, 64, 0, c4, 64, acc);
#pragma unroll
    for (int p = 0; p < 4; p++) {
        float2 v0 = up(acc[p][0]), v1 = up(acc[p][1]), v2 = up(acc[p][2]), v3 = up(acc[p][3]);
#pragma unroll
        for (int half = 0; half < 2; half++) {
            int el = eA + 2 * p + half;
            int d = sdst[el];
            float a0 = INV * (half ? v0.y : v0.x);
            float a1 = INV * (half ? v1.y : v1.x);
            float a2 = INV * (half ? v2.y : v2.x);
            float a3 = INV * (half ? v3.y : v3.x);
            float* pp = &g_f1[d * 192];
#pragma unroll
            for (int i = 0; i < 3; i++) {
                float yy = sy[i][el];
                red_v4(pp + i * 64 + c4, a0 * yy, a1 * yy, a2 * yy, a3 * yy);
            }
        }
    }
}

// ---------------- K2: fused messages + softmax-weight + aggregation ----------------
// No-max softmax: attn = exp(a)/sum(exp(a)); accumulate ea*msg and ea directly.
__global__ void __launch_bounds__(256) k2_fused(
    const float* __restrict__ pos, const float* __restrict__ alpha_dot,
    const int* __restrict__ esrc, const int* __restrict__ edst)
{
    int warp = threadIdx.x >> 5, lane = threadIdx.x & 31;
    int e = blockIdx.x * 8 + warp;
    if (e >= NE) return;
    int s = esrc[e], d = edst[e];
    float vx = pos[d * 3 + 0] - pos[s * 3 + 0];
    float vy = pos[d * 3 + 1] - pos[s * 3 + 1];
    float vz = pos[d * 3 + 2] - pos[s * 3 + 2];
    float ri = rsqrtf(vx * vx + vy * vy + vz * vz + 1e-9f);
    float y0 = vx * ri, y1 = vy * ri, y2 = vz * ri;

    int c = lane << 1;                 // channels c, c+1 (same head h = lane>>2)
    float2 s0 = *reinterpret_cast<const float2*>(&g_f0[s * 64 + c]);
    const float* f1p = &g_f1[s * 192 + c];
    float2 sv0 = *reinterpret_cast<const float2*>(f1p + 0 * 64);
    float2 sv1 = *reinterpret_cast<const float2*>(f1p + 1 * 64);
    float2 sv2 = *reinterpret_cast<const float2*>(f1p + 2 * 64);

    const __half2* wp = reinterpret_cast<const __half2*>(&g_wattn_h[(long long)e * 320 + c]);
    float2 w0 = __half22float2(wp[0]);
    float2 w1 = __half22float2(wp[32]);
    float2 w2 = __half22float2(wp[64]);
    float2 w3 = __half22float2(wp[96]);
    float2 w4 = __half22float2(wp[128]);

    const float IS3 = 0.57735026918962576f;
    const float IS2 = 0.70710678118654752f;

    // msg0
    float dvx = sv0.x * y0 + sv1.x * y1 + sv2.x * y2;
    float dvy = sv0.y * y0 + sv1.y * y1 + sv2.y * y2;
    float m0x = w0.x * s0.x + w3.x * dvx * IS3;
    float m0y = w0.y * s0.y + w3.y * dvy * IS3;

    // cross(s1, Y) per channel
    float cx0x = sv1.x * y2 - sv2.x * y1, cx1x = sv2.x * y0 - sv0.x * y2, cx2x = sv0.x * y1 - sv1.x * y0;
    float cx0y = sv1.y * y2 - sv2.y * y1, cx1y = sv2.y * y0 - sv0.y * y2, cx2y = sv0.y * y1 - sv1.y * y0;
    float w1sx = w1.x * s0.x, w1sy = w1.y * s0.y;
    float m1x0 = w1sx * y0 + w2.x * sv0.x + w4.x * cx0x * IS2;
    float m1x1 = w1sx * y1 + w2.x * sv1.x + w4.x * cx1x * IS2;
    float m1x2 = w1sx * y2 + w2.x * sv2.x + w4.x * cx2x * IS2;
    float m1y0 = w1sy * y0 + w2.y * sv0.y + w4.y * cx0y * IS2;
    float m1y1 = w1sy * y1 + w2.y * sv1.y + w4.y * cx1y * IS2;
    float m1y2 = w1sy * y2 + w2.y * sv2.y + w4.y * cx2y * IS2;

    // logit for head h = lane>>2: sum of slr*alpha over the head's 8 channels
    float slrx = 0.2f * m0x + 0.8f * m0x * sigf(m0x);
    float slry = 0.2f * m0y + 0.8f * m0y * sigf(m0y);
    float p = slrx * alpha_dot[c] + slry * alpha_dot[c + 1];
    p += __shfl_xor_sync(0xffffffffu, p, 2);
    p += __shfl_xor_sync(0xffffffffu, p, 1);
    float ea = __expf(p);

    if ((lane & 3) == 0) atomicAdd(&g_z[d * 8 + (lane >> 2)], ea);

    red_v2(&g_agg0[d * 64 + c], ea * m0x, ea * m0y);
    float* ap = &g_agg1[d * 192 + c];
    red_v2(ap + 0 * 64, ea * m1x0, ea * m1y0);
    red_v2(ap + 1 * 64, ea * m1x1, ea * m1y1);
    red_v2(ap + 2 * 64, ea * m1x2, ea * m1y2);
}

// ---------------- K4: node update ----------------
__global__ void __launch_bounds__(256) k4_node(
    const float* __restrict__ P0, const float* __restrict__ P1,
    const float* __restrict__ W1s, const float* __restrict__ b1s,
    const float* __restrict__ W1v, const float* __restrict__ W2s,
    const float* __restrict__ b2s, const float* __restrict__ W2v,
    float* __restrict__ out)
{
    __shared__ float sm[8][832];
    int warp = threadIdx.x >> 5, lane = threadIdx.x & 31;
    int n = blockIdx.x * 8 + warp;
    if (n >= NN) return;
    float* sA0 = sm[warp];
    float* sA1 = sm[warp] + 64;
    float* sF0 = sm[warp] + 256;
    float* sF1 = sm[warp] + 320;
    float* sMS = sm[warp] + 512;
    float* sG  = sm[warp] + 576;
    float* sMV = sm[warp] + 640;

    int c0 = lane, c1 = lane + 32;
    float za = g_z[n * 8 + (lane >> 3)];
    float zb = g_z[n * 8 + 4 + (lane >> 3)];
    float rza = za > 0.f ? __fdividef(1.f, za) : 0.f;
    float rzb = zb > 0.f ? __fdividef(1.f, zb) : 0.f;
    sA0[c0] = g_agg0[n * 64 + c0] * rza;
    sA0[c1] = g_agg0[n * 64 + c1] * rzb;
#pragma unroll
    for (int i = 0; i < 3; i++) {
        sA1[c0 * 3 + i] = g_agg1[n * 192 + i * 64 + c0] * rza;
        sA1[c1 * 3 + i] = g_agg1[n * 192 + i * 64 + c1] * rzb;
    }
    sF0[c0] = g_f0[n * 64 + c0];
    sF0[c1] = g_f0[n * 64 + c1];
#pragma unroll
    for (int i = 0; i < 3; i++) {
        sF1[c0 * 3 + i] = g_f1[n * 192 + i * 64 + c0];
        sF1[c1 * 3 + i] = g_f1[n * 192 + i * 64 + c1];
    }
    __syncwarp();

    float f0a = sF0[c0], f0b = sF0[c1];
    float f1a[3] = {sF1[c0 * 3], sF1[c0 * 3 + 1], sF1[c0 * 3 + 2]};
    float f1b[3] = {sF1[c1 * 3], sF1[c1 * 3 + 1], sF1[c1 * 3 + 2]};
#pragma unroll 4
    for (int c = 0; c < 64; c++) {
        float r = sA0[c];
        f0a += r * P0[c * 64 + c0];
        f0b += r * P0[c * 64 + c1];
        float wa = P1[c * 64 + c0], wbv = P1[c * 64 + c1];
#pragma unroll
        for (int i = 0; i < 3; i++) {
            f1a[i] += sA1[c * 3 + i] * wa;
            f1b[i] += sA1[c * 3 + i] * wbv;
        }
    }
    __syncwarp();
    sF0[c0] = f0a; sF0[c1] = f0b;
#pragma unroll
    for (int i = 0; i < 3; i++) { sF1[c0 * 3 + i] = f1a[i]; sF1[c1 * 3 + i] = f1b[i]; }
    __syncwarp();

    float hs0 = b1s[c0], hs1 = b1s[c1], hs2 = b1s[64 + c0], hs3 = b1s[64 + c1];
#pragma unroll 4
    for (int c = 0; c < 64; c++) {
        float r = sF0[c];
        hs0 += r * W1s[c * 128 + c0];
        hs1 += r * W1s[c * 128 + c1];
        hs2 += r * W1s[c * 128 + 64 + c0];
        hs3 += r * W1s[c * 128 + 64 + c1];
    }
    sMS[c0] = siluf(hs0); sMS[c1] = siluf(hs1);
    sG[c0] = sigf(hs2);   sG[c1] = sigf(hs3);
    __syncwarp();

    float mva[3] = {0, 0, 0}, mvb[3] = {0, 0, 0};
#pragma unroll 4
    for (int c = 0; c < 64; c++) {
        float wa = W1v[c * 64 + c0], wbv = W1v[c * 64 + c1];
#pragma unroll
        for (int i = 0; i < 3; i++) {
            mva[i] += sF1[c * 3 + i] * wa;
            mvb[i] += sF1[c * 3 + i] * wbv;
        }
    }
    float ga = sG[c0], gb = sG[c1];
#pragma unroll
    for (int i = 0; i < 3; i++) { sMV[c0 * 3 + i] = mva[i] * ga; sMV[c1 * 3 + i] = mvb[i] * gb; }
    __syncwarp();

    float o0a = sF0[c0] + b2s[c0], o0b = sF0[c1] + b2s[c1];
    float o1a[3] = {sF1[c0 * 3], sF1[c0 * 3 + 1], sF1[c0 * 3 + 2]};
    float o1b[3] = {sF1[c1 * 3], sF1[c1 * 3 + 1], sF1[c1 * 3 + 2]};
#pragma unroll 4
    for (int c = 0; c < 64; c++) {
        float r = sMS[c];
        o0a += r * W2s[c * 64 + c0];
        o0b += r * W2s[c * 64 + c1];
        float wa = W2v[c * 64 + c0], wbv = W2v[c * 64 + c1];
#pragma unroll
        for (int i = 0; i < 3; i++) {
            o1a[i] += sMV[c * 3 + i] * wa;
            o1b[i] += sMV[c * 3 + i] * wbv;
        }
    }

    long long ob = (long long)n * 256;
    out[ob + c0] = o0a;
    out[ob + c1] = o0b;
#pragma unroll
    for (int i = 0; i < 3; i++) {
        out[ob + 64 + c0 * 3 + i] = o1a[i];
        out[ob + 64 + c1 * 3 + i] = o1b[i];
    }
}

// ---------------- launch ----------------
extern "C" void kernel_launch(void* const* d_in, const int* in_sizes, int n_in,
                              void* d_out, int out_size) {
    const float* pos       = (const float*)d_in[0];
    const float* embed_W   = (const float*)d_in[1];
    const float* exp_w     = (const float*)d_in[2];
    const float* rad_W1    = (const float*)d_in[3];
    const float* rad_b1    = (const float*)d_in[4];
    const float* rad_W2    = (const float*)d_in[5];
    const float* rad_b2    = (const float*)d_in[6];
    const float* rad_Wdeg  = (const float*)d_in[7];
    const float* rad_bdeg  = (const float*)d_in[8];
    const float* rad_Wattn = (const float*)d_in[9];
    const float* rad_battn = (const float*)d_in[10];
    const float* deg_proj0 = (const float*)d_in[11];
    const float* deg_proj1 = (const float*)d_in[12];
    const float* alpha_dot = (const float*)d_in[13];
    const float* out_proj0 = (const float*)d_in[14];
    const float* out_proj1 = (const float*)d_in[15];
    const float* ffn_W1s   = (const float*)d_in[16];
    const float* ffn_b1s   = (const float*)d_in[17];
    const float* ffn_W1v   = (const float*)d_in[18];
    const float* ffn_W2s   = (const float*)d_in[19];
    const float* ffn_b2s   = (const float*)d_in[20];
    const float* ffn_W2v   = (const float*)d_in[21];
    const int* node_atom   = (const int*)d_in[22];
    const int* edge_src    = (const int*)d_in[23];
    const int* edge_dst    = (const int*)d_in[24];
    float* out = (float*)d_out;

    k0_init<<<1024, 256>>>(embed_W, node_atom);
    k1_edge<<<NE / 64, 128>>>(pos, exp_w, rad_W1, rad_b1, rad_W2, rad_b2,
                              rad_Wdeg, rad_bdeg, rad_Wattn, rad_battn,
                              deg_proj0, deg_proj1, edge_src, edge_dst);
    k2_fused<<<NE / 8, 256>>>(pos, alpha_dot, edge_src, edge_dst);
    k4_node<<<NN / 8, 256>>>(out_proj0, out_proj1, ffn_W1s, ffn_b1s,
                             ffn_W1v, ffn_W2s, ffn_b2s, ffn_W2v, out);
}

// round 9
// speedup vs baseline: 1.6163x; 1.0214x over previous
#include <cuda_runtime.h>
#include <cuda_fp16.h>
#include <math.h>
#include <stdint.h>

#define NN 50000
#define NE 800000
#define LDS_S 66

// ---------------- scratch (device globals) ----------------
__device__ float g_f0[NN * 64];
__device__ float g_f1[NN * 192];          // [n][3][64]
__device__ float g_agg0[NN * 64];
__device__ float g_agg1[NN * 192];        // [n][3][64]
__device__ float g_z[NN * 8];
__device__ __half g_wattn_h[256000000];   // E*320

typedef unsigned long long u64;

// ---------------- helpers ----------------
__device__ __forceinline__ float siluf(float x) { return __fdividef(x, 1.f + __expf(-x)); }
__device__ __forceinline__ float sigf(float x) { return __fdividef(1.f, 1.f + __expf(-x)); }

__device__ __forceinline__ u64 pk(float x) {
    u64 r; asm("mov.b64 %0, {%1, %1};" : "=l"(r) : "f"(x)); return r;
}
__device__ __forceinline__ void fma2(u64& d, u64 a, u64 b) {
    asm("fma.rn.f32x2 %0, %1, %2, %0;" : "+l"(d) : "l"(a), "l"(b));
}
__device__ __forceinline__ float2 up(u64 a) {
    float2 v; asm("mov.b64 {%0, %1}, %2;" : "=f"(v.x), "=f"(v.y) : "l"(a)); return v;
}

__device__ __forceinline__ void red_v2(float* p, float a, float b) {
    asm volatile("{ .reg .u64 q; cvta.to.global.u64 q, %0; red.global.add.v2.f32 [q], {%1, %2}; }"
                 :: "l"(p), "f"(a), "f"(b) : "memory");
}
__device__ __forceinline__ void red_v4(float* p, float a, float b, float c, float d) {
    asm volatile("{ .reg .u64 q; cvta.to.global.u64 q, %0; red.global.add.v4.f32 [q], {%1, %2, %3, %4}; }"
                 :: "l"(p), "f"(a), "f"(b), "f"(c), "f"(d) : "memory");
}

// ---------------- K0: init node state ----------------
__global__ void k0_init(const float* __restrict__ embed_W, const int* __restrict__ node_atom) {
    int stride = gridDim.x * blockDim.x;
    for (int i = blockIdx.x * blockDim.x + threadIdx.x; i < NN * 192; i += stride) {
        g_f1[i] = 0.f;
        g_agg1[i] = 0.f;
        if (i < NN * 64) {
            int n = i >> 6, c = i & 63;
            g_f0[i] = embed_W[node_atom[n] * 64 + c];
            g_agg0[i] = 0.f;
        }
        if (i < NN * 8) g_z[i] = 0.f;
    }
}

// ---------------- k-major GEMM, 8 rows (4 pairs) per thread ----------------
__device__ __forceinline__ void gemm_t(const float* __restrict__ As, int eA,
                                       const float* __restrict__ Bg, int ldb,
                                       int colbase, int c4, int K,
                                       u64 acc[4][4]) {
#pragma unroll
    for (int p = 0; p < 4; p++)
#pragma unroll
        for (int j = 0; j < 4; j++) acc[p][j] = 0ull;
    const float* Bp = Bg + colbase + c4;
#pragma unroll 4
    for (int k = 0; k < K; k++) {
        const u64* ap = reinterpret_cast<const u64*>(As + k * LDS_S + eA);
        u64 a0 = ap[0], a1 = ap[1], a2 = ap[2], a3 = ap[3];
        float4 b = *reinterpret_cast<const float4*>(Bp + k * ldb);
        u64 bx = pk(b.x), by = pk(b.y), bz = pk(b.z), bw = pk(b.w);
        fma2(acc[0][0], a0, bx); fma2(acc[0][1], a0, by); fma2(acc[0][2], a0, bz); fma2(acc[0][3], a0, bw);
        fma2(acc[1][0], a1, bx); fma2(acc[1][1], a1, by); fma2(acc[1][2], a1, bz); fma2(acc[1][3], a1, bw);
        fma2(acc[2][0], a2, bx); fma2(acc[2][1], a2, by); fma2(acc[2][2], a2, bz); fma2(acc[2][3], a2, bw);
        fma2(acc[3][0], a3, bx); fma2(acc[3][1], a3, by); fma2(acc[3][2], a3, bz); fma2(acc[3][3], a3, bw);
    }
}

// k-major GEMM, 4 rows (2 pairs) per thread, K=64
__device__ __forceinline__ void gemm_t2(const float* __restrict__ As, int eA,
                                        const float* __restrict__ Bg, int ldb,
                                        int colbase, int c4,
                                        u64 acc[2][4]) {
#pragma unroll
    for (int p = 0; p < 2; p++)
#pragma unroll
        for (int j = 0; j < 4; j++) acc[p][j] = 0ull;
    const float* Bp = Bg + colbase + c4;
#pragma unroll 4
    for (int k = 0; k < 64; k++) {
        const u64* ap = reinterpret_cast<const u64*>(As + k * LDS_S + eA);
        u64 a0 = ap[0], a1 = ap[1];
        float4 b = *reinterpret_cast<const float4*>(Bp + k * ldb);
        u64 bx = pk(b.x), by = pk(b.y), bz = pk(b.z), bw = pk(b.w);
        fma2(acc[0][0], a0, bx); fma2(acc[0][1], a0, by); fma2(acc[0][2], a0, bz); fma2(acc[0][3], a0, bw);
        fma2(acc[1][0], a1, bx); fma2(acc[1][1], a1, by); fma2(acc[1][2], a1, bz); fma2(acc[1][3], a1, bw);
    }
}

// ---------------- K1: edge-tiled radial MLP + degree scatter + w_attn ----------------
__global__ void __launch_bounds__(128) k1_edge(
    const float* __restrict__ pos, const float* __restrict__ exp_w,
    const float* __restrict__ W1, const float* __restrict__ b1,
    const float* __restrict__ W2, const float* __restrict__ b2,
    const float* __restrict__ Wdeg, const float* __restrict__ bdeg,
    const float* __restrict__ Wattn, const float* __restrict__ battn,
    const float* __restrict__ P0, const float* __restrict__ P1,
    const int* __restrict__ esrc, const int* __restrict__ edst)
{
    __shared__ float SA[64 * LDS_S];
    __shared__ float SB[64 * LDS_S];
    __shared__ float sy[3][64];
    __shared__ int sdst[64];
    __shared__ float stmp[2][64];

    int tid = threadIdx.x;
    int cg = tid & 15, c4 = cg << 2;
    int eg = tid >> 4, eA = eg << 3;
    int ebase = blockIdx.x * 64;

    if (tid < 64) {
        int e = ebase + tid;
        int s = esrc[e], d = edst[e];
        float vx = pos[d * 3 + 0] - pos[s * 3 + 0];
        float vy = pos[d * 3 + 1] - pos[s * 3 + 1];
        float vz = pos[d * 3 + 2] - pos[s * 3 + 2];
        float dist = sqrtf(vx * vx + vy * vy + vz * vz + 1e-9f);
        float ri = 1.f / dist;
        const float PI_ = 3.14159265358979323846f;
        float cut = (dist < 5.0f) ? 0.5f * (__cosf(PI_ * dist * 0.2f) + 1.f) : 0.f;
        sdst[tid] = d;
        sy[0][tid] = vx * ri; sy[1][tid] = vy * ri; sy[2][tid] = vz * ri;
        stmp[0][tid] = cut;
        stmp[1][tid] = __expf(-dist);
    }
    __syncthreads();

    {
        const float START = 0.006737946999085467f;
        const float STEP = (1.0f - START) / 49.0f;
        const float BETA = 1.0f / ((0.04f * (1.0f - START)) * (0.04f * (1.0f - START)));
        int er = tid & 63, k0 = tid >> 6;
        float cut = stmp[0][er], expd = stmp[1][er];
        for (int k = k0; k < 50; k += 2) {
            float t = expd - (START + (float)k * STEP);
            SA[k * LDS_S + er] = cut * __expf(-BETA * t * t);
        }
    }
    __syncthreads();

    u64 acc[4][4];

    gemm_t(SA, eA, W1, 64, 0, c4, 50, acc);
    {
#pragma unroll
        for (int j = 0; j < 4; j++) {
            float bb = b1[c4 + j];
#pragma unroll
            for (int p = 0; p < 4; p++) {
                float2 v = up(acc[p][j]);
                v.x = siluf(v.x + bb); v.y = siluf(v.y + bb);
                *reinterpret_cast<float2*>(&SB[(c4 + j) * LDS_S + eA + 2 * p]) = v;
            }
        }
    }
    __syncthreads();

    gemm_t(SB, eA, W2, 64, 0, c4, 64, acc);
    {
#pragma unroll
        for (int j = 0; j < 4; j++) {
            float bb = b2[c4 + j];
#pragma unroll
            for (int p = 0; p < 4; p++) {
                float2 v = up(acc[p][j]);
                v.x = siluf(v.x + bb); v.y = siluf(v.y + bb);
                *reinterpret_cast<float2*>(&SA[(c4 + j) * LDS_S + eA + 2 * p]) = v;
            }
        }
    }
    __syncthreads();

    for (int ch = 0; ch < 5; ch++) {
        gemm_t(SA, eA, Wattn, 320, ch * 64, c4, 64, acc);
        int col = ch * 64 + c4;
        float b0v = battn[col], b1v = battn[col + 1], b2v = battn[col + 2], b3v = battn[col + 3];
#pragma unroll
        for (int p = 0; p < 4; p++) {
            float2 v0 = up(acc[p][0]), v1 = up(acc[p][1]), v2 = up(acc[p][2]), v3 = up(acc[p][3]);
            long long wbA = (long long)(ebase + eA + 2 * p) * 320 + col;
            long long wbB = wbA + 320;
            *reinterpret_cast<__half2*>(&g_wattn_h[wbA])     = __floats2half2_rn(v0.x + b0v, v1.x + b1v);
            *reinterpret_cast<__half2*>(&g_wattn_h[wbA + 2]) = __floats2half2_rn(v2.x + b2v, v3.x + b3v);
            *reinterpret_cast<__half2*>(&g_wattn_h[wbB])     = __floats2half2_rn(v0.y + b0v, v1.y + b1v);
            *reinterpret_cast<__half2*>(&g_wattn_h[wbB + 2]) = __floats2half2_rn(v2.y + b2v, v3.y + b3v);
        }
    }

    const float INV = 0.25f;

    gemm_t(SA, eA, Wdeg, 128, 0, c4, 64, acc);
    {
#pragma unroll
        for (int j = 0; j < 4; j++) {
            float bb = bdeg[c4 + j], ee = exp_w[c4 + j];
#pragma unroll
            for (int p = 0; p < 4; p++) {
                float2 v = up(acc[p][j]);
                v.x = (v.x + bb) * ee; v.y = (v.y + bb) * ee;
                *reinterpret_cast<float2*>(&SB[(c4 + j) * LDS_S + eA + 2 * p]) = v;
            }
        }
    }
    __syncthreads();

    gemm_t(SB, eA, P0, 64, 0, c4, 64, acc);
#pragma unroll
    for (int p = 0; p < 4; p++) {
        int dA = sdst[eA + 2 * p], dB = sdst[eA + 2 * p + 1];
        float2 v0 = up(acc[p][0]), v1 = up(acc[p][1]), v2 = up(acc[p][2]), v3 = up(acc[p][3]);
        red_v4(&g_f0[dA * 64 + c4], INV * v0.x, INV * v1.x, INV * v2.x, INV * v3.x);
        red_v4(&g_f0[dB * 64 + c4], INV * v0.y, INV * v1.y, INV * v2.y, INV * v3.y);
    }
    __syncthreads();

    gemm_t(SA, eA, Wdeg, 128, 64, c4, 64, acc);
    {
#pragma unroll
        for (int j = 0; j < 4; j++) {
            float bb = bdeg[64 + c4 + j], ee = exp_w[c4 + j];
#pragma unroll
            for (int p = 0; p < 4; p++) {
                float2 v = up(acc[p][j]);
                v.x = (v.x + bb) * ee; v.y = (v.y + bb) * ee;
                *reinterpret_cast<float2*>(&SB[(c4 + j) * LDS_S + eA + 2 * p]) = v;
            }
        }
    }
    __syncthreads();

    gemm_t(SB, eA, P1, 64, 0, c4, 64, acc);
#pragma unroll
    for (int p = 0; p < 4; p++) {
        float2 v0 = up(acc[p][0]), v1 = up(acc[p][1]), v2 = up(acc[p][2]), v3 = up(acc[p][3]);
#pragma unroll
        for (int half = 0; half < 2; half++) {
            int el = eA + 2 * p + half;
            int d = sdst[el];
            float a0 = INV * (half ? v0.y : v0.x);
            float a1 = INV * (half ? v1.y : v1.x);
            float a2 = INV * (half ? v2.y : v2.x);
            float a3 = INV * (half ? v3.y : v3.x);
            float* pp = &g_f1[d * 192];
#pragma unroll
            for (int i = 0; i < 3; i++) {
                float yy = sy[i][el];
                red_v4(pp + i * 64 + c4, a0 * yy, a1 * yy, a2 * yy, a3 * yy);
            }
        }
    }
}

// ---------------- K2: fused messages + softmax-weight + aggregation ----------------
__global__ void __launch_bounds__(256) k2_fused(
    const float* __restrict__ pos, const float* __restrict__ alpha_dot,
    const int* __restrict__ esrc, const int* __restrict__ edst)
{
    int warp = threadIdx.x >> 5, lane = threadIdx.x & 31;
    int e = blockIdx.x * 8 + warp;
    if (e >= NE) return;
    int s = esrc[e], d = edst[e];
    float vx = pos[d * 3 + 0] - pos[s * 3 + 0];
    float vy = pos[d * 3 + 1] - pos[s * 3 + 1];
    float vz = pos[d * 3 + 2] - pos[s * 3 + 2];
    float ri = rsqrtf(vx * vx + vy * vy + vz * vz + 1e-9f);
    float y0 = vx * ri, y1 = vy * ri, y2 = vz * ri;

    int c = lane << 1;
    float2 s0 = *reinterpret_cast<const float2*>(&g_f0[s * 64 + c]);
    const float* f1p = &g_f1[s * 192 + c];
    float2 sv0 = *reinterpret_cast<const float2*>(f1p + 0 * 64);
    float2 sv1 = *reinterpret_cast<const float2*>(f1p + 1 * 64);
    float2 sv2 = *reinterpret_cast<const float2*>(f1p + 2 * 64);

    const __half2* wp = reinterpret_cast<const __half2*>(&g_wattn_h[(long long)e * 320 + c]);
    float2 w0 = __half22float2(wp[0]);
    float2 w1 = __half22float2(wp[32]);
    float2 w2 = __half22float2(wp[64]);
    float2 w3 = __half22float2(wp[96]);
    float2 w4 = __half22float2(wp[128]);

    const float IS3 = 0.57735026918962576f;
    const float IS2 = 0.70710678118654752f;

    float dvx = sv0.x * y0 + sv1.x * y1 + sv2.x * y2;
    float dvy = sv0.y * y0 + sv1.y * y1 + sv2.y * y2;
    float m0x = w0.x * s0.x + w3.x * dvx * IS3;
    float m0y = w0.y * s0.y + w3.y * dvy * IS3;

    float cx0x = sv1.x * y2 - sv2.x * y1, cx1x = sv2.x * y0 - sv0.x * y2, cx2x = sv0.x * y1 - sv1.x * y0;
    float cx0y = sv1.y * y2 - sv2.y * y1, cx1y = sv2.y * y0 - sv0.y * y2, cx2y = sv0.y * y1 - sv1.y * y0;
    float w1sx = w1.x * s0.x, w1sy = w1.y * s0.y;
    float m1x0 = w1sx * y0 + w2.x * sv0.x + w4.x * cx0x * IS2;
    float m1x1 = w1sx * y1 + w2.x * sv1.x + w4.x * cx1x * IS2;
    float m1x2 = w1sx * y2 + w2.x * sv2.x + w4.x * cx2x * IS2;
    float m1y0 = w1sy * y0 + w2.y * sv0.y + w4.y * cx0y * IS2;
    float m1y1 = w1sy * y1 + w2.y * sv1.y + w4.y * cx1y * IS2;
    float m1y2 = w1sy * y2 + w2.y * sv2.y + w4.y * cx2y * IS2;

    float slrx = 0.2f * m0x + 0.8f * m0x * sigf(m0x);
    float slry = 0.2f * m0y + 0.8f * m0y * sigf(m0y);
    float p = slrx * alpha_dot[c] + slry * alpha_dot[c + 1];
    p += __shfl_xor_sync(0xffffffffu, p, 2);
    p += __shfl_xor_sync(0xffffffffu, p, 1);
    float ea = __expf(p);

    if ((lane & 3) == 0) atomicAdd(&g_z[d * 8 + (lane >> 2)], ea);

    red_v2(&g_agg0[d * 64 + c], ea * m0x, ea * m0y);
    float* ap = &g_agg1[d * 192 + c];
    red_v2(ap + 0 * 64, ea * m1x0, ea * m1y0);
    red_v2(ap + 1 * 64, ea * m1x1, ea * m1y1);
    red_v2(ap + 2 * 64, ea * m1x2, ea * m1y2);
}

// ---------------- K4: tiled node update (64 nodes / block) ----------------
#define SOFF_T   0
#define SOFF_F0  4224
#define SOFF_F10 8448
#define SOFF_F11 12672
#define SOFF_F12 16896
#define SOFF_G   21120
#define K4_SMEM  (25344 * 4)

__global__ void __launch_bounds__(256) k4_node(
    const float* __restrict__ P0, const float* __restrict__ P1,
    const float* __restrict__ W1s, const float* __restrict__ b1s,
    const float* __restrict__ W1v, const float* __restrict__ W2s,
    const float* __restrict__ b2s, const float* __restrict__ W2v,
    float* __restrict__ out)
{
    extern __shared__ float sm4[];
    float* T  = sm4 + SOFF_T;
    float* F0 = sm4 + SOFF_F0;
    float* F1a = sm4 + SOFF_F10;
    float* F1b = sm4 + SOFF_F11;
    float* F1c = sm4 + SOFF_F12;
    float* G  = sm4 + SOFF_G;
    float* F1arr[3] = {F1a, F1b, F1c};

    int tid = threadIdx.x;
    int cg = tid & 15, c4 = cg << 2;
    int eA = (tid >> 4) << 2;            // 4 nodes per thread (2 pairs)
    int nbase = blockIdx.x * 64;

    // stage normalized attention aggregates (T = agg0/z, F1_i = agg1_i/z)
    for (int idx = tid; idx < 4096; idx += 256) {
        int node = idx >> 6, c = idx & 63;
        int n = nbase + node; if (n >= NN) n = NN - 1;
        float z = g_z[n * 8 + (c >> 3)];
        float rz = z > 0.f ? __fdividef(1.f, z) : 0.f;
        T[c * LDS_S + node]   = g_agg0[n * 64 + c] * rz;
        F1a[c * LDS_S + node] = g_agg1[n * 192 + c] * rz;
        F1b[c * LDS_S + node] = g_agg1[n * 192 + 64 + c] * rz;
        F1c[c * LDS_S + node] = g_agg1[n * 192 + 128 + c] * rz;
    }
    __syncthreads();

    u64 acc[2][4];

    // F0 = f0 + A0 @ P0
    gemm_t2(T, eA, P0, 64, 0, c4, acc);
#pragma unroll
    for (int p = 0; p < 2; p++) {
        int na = nbase + eA + 2 * p, nb = na + 1;
        int la = na < NN ? na : NN - 1, lb = nb < NN ? nb : NN - 1;
        float4 ra = *reinterpret_cast<const float4*>(&g_f0[la * 64 + c4]);
        float4 rb = *reinterpret_cast<const float4*>(&g_f0[lb * 64 + c4]);
        float2 v0 = up(acc[p][0]), v1 = up(acc[p][1]), v2 = up(acc[p][2]), v3 = up(acc[p][3]);
        int ea2 = eA + 2 * p;
        F0[(c4 + 0) * LDS_S + ea2] = v0.x + ra.x;  F0[(c4 + 0) * LDS_S + ea2 + 1] = v0.y + rb.x;
        F0[(c4 + 1) * LDS_S + ea2] = v1.x + ra.y;  F0[(c4 + 1) * LDS_S + ea2 + 1] = v1.y + rb.y;
        F0[(c4 + 2) * LDS_S + ea2] = v2.x + ra.z;  F0[(c4 + 2) * LDS_S + ea2 + 1] = v2.y + rb.z;
        F0[(c4 + 3) * LDS_S + ea2] = v3.x + ra.w;  F0[(c4 + 3) * LDS_S + ea2 + 1] = v3.y + rb.w;
    }

    // F1_i = f1_i + A1_i @ P1 (in place, sync before overwrite)
#pragma unroll
    for (int i = 0; i < 3; i++) {
        float* Fi = F1arr[i];
        gemm_t2(Fi, eA, P1, 64, 0, c4, acc);
        __syncthreads();
#pragma unroll
        for (int p = 0; p < 2; p++) {
            int na = nbase + eA + 2 * p, nb = na + 1;
            int la = na < NN ? na : NN - 1, lb = nb < NN ? nb : NN - 1;
            float4 ra = *reinterpret_cast<const float4*>(&g_f1[la * 192 + i * 64 + c4]);
            float4 rb = *reinterpret_cast<const float4*>(&g_f1[lb * 192 + i * 64 + c4]);
            float2 v0 = up(acc[p][0]), v1 = up(acc[p][1]), v2 = up(acc[p][2]), v3 = up(acc[p][3]);
            int ea2 = eA + 2 * p;
            Fi[(c4 + 0) * LDS_S + ea2] = v0.x + ra.x;  Fi[(c4 + 0) * LDS_S + ea2 + 1] = v0.y + rb.x;
            Fi[(c4 + 1) * LDS_S + ea2] = v1.x + ra.y;  Fi[(c4 + 1) * LDS_S + ea2 + 1] = v1.y + rb.y;
            Fi[(c4 + 2) * LDS_S + ea2] = v2.x + ra.z;  Fi[(c4 + 2) * LDS_S + ea2 + 1] = v2.y + rb.z;
            Fi[(c4 + 3) * LDS_S + ea2] = v3.x + ra.w;  Fi[(c4 + 3) * LDS_S + ea2 + 1] = v3.y + rb.w;
        }
        __syncthreads();
    }

    // FFN layer 1: T = silu(F0@W1s[:, :64] + b), G = sigmoid(F0@W1s[:, 64:] + b)
    gemm_t2(F0, eA, W1s, 128, 0, c4, acc);
    {
#pragma unroll
        for (int j = 0; j < 4; j++) {
            float bb = b1s[c4 + j];
#pragma unroll
            for (int p = 0; p < 2; p++) {
                float2 v = up(acc[p][j]);
                T[(c4 + j) * LDS_S + eA + 2 * p]     = siluf(v.x + bb);
                T[(c4 + j) * LDS_S + eA + 2 * p + 1] = siluf(v.y + bb);
            }
        }
    }
    gemm_t2(F0, eA, W1s, 128, 64, c4, acc);
    {
#pragma unroll
        for (int j = 0; j < 4; j++) {
            float bb = b1s[64 + c4 + j];
#pragma unroll
            for (int p = 0; p < 2; p++) {
                float2 v = up(acc[p][j]);
                G[(c4 + j) * LDS_S + eA + 2 * p]     = sigf(v.x + bb);
                G[(c4 + j) * LDS_S + eA + 2 * p + 1] = sigf(v.y + bb);
            }
        }
    }
    __syncthreads();

    // out0 = F0 + mid_s @ W2s + b2s
    gemm_t2(T, eA, W2s, 64, 0, c4, acc);
#pragma unroll
    for (int p = 0; p < 2; p++) {
        float2 v0 = up(acc[p][0]), v1 = up(acc[p][1]), v2 = up(acc[p][2]), v3 = up(acc[p][3]);
#pragma unroll
        for (int half = 0; half < 2; half++) {
            int node = eA + 2 * p + half;
            int n = nbase + node;
            if (n < NN) {
                float4 o;
                o.x = (half ? v0.y : v0.x) + b2s[c4 + 0] + F0[(c4 + 0) * LDS_S + node];
                o.y = (half ? v1.y : v1.x) + b2s[c4 + 1] + F0[(c4 + 1) * LDS_S + node];
                o.z = (half ? v2.y : v2.x) + b2s[c4 + 2] + F0[(c4 + 2) * LDS_S + node];
                o.w = (half ? v3.y : v3.x) + b2s[c4 + 3] + F0[(c4 + 3) * LDS_S + node];
                *reinterpret_cast<float4*>(&out[(long long)n * 256 + c4]) = o;
            }
        }
    }

    // vector FFN: for each component i: mid_v = (F1_i@W1v)*G -> T; out1_i = F1_i + T@W2v
#pragma unroll
    for (int i = 0; i < 3; i++) {
        float* Fi = F1arr[i];
        gemm_t2(Fi, eA, W1v, 64, 0, c4, acc);
        __syncthreads();   // everyone done reading T (out0 / previous i)
        {
#pragma unroll
            for (int j = 0; j < 4; j++) {
#pragma unroll
                for (int p = 0; p < 2; p++) {
                    float2 v = up(acc[p][j]);
                    int node = eA + 2 * p;
                    T[(c4 + j) * LDS_S + node]     = v.x * G[(c4 + j) * LDS_S + node];
                    T[(c4 + j) * LDS_S + node + 1] = v.y * G[(c4 + j) * LDS_S + node + 1];
                }
            }
        }
        __syncthreads();
        gemm_t2(T, eA, W2v, 64, 0, c4, acc);
#pragma unroll
        for (int p = 0; p < 2; p++) {
            float2 v0 = up(acc[p][0]), v1 = up(acc[p][1]), v2 = up(acc[p][2]), v3 = up(acc[p][3]);
#pragma unroll
            for (int half = 0; half < 2; half++) {
                int node = eA + 2 * p + half;
                int n = nbase + node;
                if (n < NN) {
                    long long ob = (long long)n * 256 + 64;
                    out[ob + (c4 + 0) * 3 + i] = (half ? v0.y : v0.x) + Fi[(c4 + 0) * LDS_S + node];
                    out[ob + (c4 + 1) * 3 + i] = (half ? v1.y : v1.x) + Fi[(c4 + 1) * LDS_S + node];
                    out[ob + (c4 + 2) * 3 + i] = (half ? v2.y : v2.x) + Fi[(c4 + 2) * LDS_S + node];
                    out[ob + (c4 + 3) * 3 + i] = (half ? v3.y : v3.x) + Fi[(c4 + 3) * LDS_S + node];
                }
            }
        }
    }
}

// ---------------- launch ----------------
extern "C" void kernel_launch(void* const* d_in, const int* in_sizes, int n_in,
                              void* d_out, int out_size) {
    const float* pos       = (const float*)d_in[0];
    const float* embed_W   = (const float*)d_in[1];
    const float* exp_w     = (const float*)d_in[2];
    const float* rad_W1    = (const float*)d_in[3];
    const float* rad_b1    = (const float*)d_in[4];
    const float* rad_W2    = (const float*)d_in[5];
    const float* rad_b2    = (const float*)d_in[6];
    const float* rad_Wdeg  = (const float*)d_in[7];
    const float* rad_bdeg  = (const float*)d_in[8];
    const float* rad_Wattn = (const float*)d_in[9];
    const float* rad_battn = (const float*)d_in[10];
    const float* deg_proj0 = (const float*)d_in[11];
    const float* deg_proj1 = (const float*)d_in[12];
    const float* alpha_dot = (const float*)d_in[13];
    const float* out_proj0 = (const float*)d_in[14];
    const float* out_proj1 = (const float*)d_in[15];
    const float* ffn_W1s   = (const float*)d_in[16];
    const float* ffn_b1s   = (const float*)d_in[17];
    const float* ffn_W1v   = (const float*)d_in[18];
    const float* ffn_W2s   = (const float*)d_in[19];
    const float* ffn_b2s   = (const float*)d_in[20];
    const float* ffn_W2v   = (const float*)d_in[21];
    const int* node_atom   = (const int*)d_in[22];
    const int* edge_src    = (const int*)d_in[23];
    const int* edge_dst    = (const int*)d_in[24];
    float* out = (float*)d_out;

    cudaFuncSetAttribute(k4_node, cudaFuncAttributeMaxDynamicSharedMemorySize, K4_SMEM);

    k0_init<<<1024, 256>>>(embed_W, node_atom);
    k1_edge<<<NE / 64, 128>>>(pos, exp_w, rad_W1, rad_b1, rad_W2, rad_b2,
                              rad_Wdeg, rad_bdeg, rad_Wattn, rad_battn,
                              deg_proj0, deg_proj1, edge_src, edge_dst);
    k2_fused<<<NE / 8, 256>>>(pos, alpha_dot, edge_src, edge_dst);
    k4_node<<<(NN + 63) / 64, 256, K4_SMEM>>>(out_proj0, out_proj1, ffn_W1s, ffn_b1s,
                                              ffn_W1v, ffn_W2s, ffn_b2s, ffn_W2v, out);
}